// round 1
// baseline (speedup 1.0000x reference)
#include <cuda_runtime.h>
#include <math.h>

#define B_ 4
#define S_ 2048
#define D_ 1024
#define H_ 16
#define DK_ 64
#define HALF_ 32
#define SCALE_ 0.125f

// Scratch (device globals: no allocation allowed)
__device__ float g_Q[(size_t)B_ * H_ * S_ * DK_];
__device__ float g_K[(size_t)B_ * H_ * S_ * DK_];
__device__ float g_V[(size_t)B_ * H_ * S_ * DK_];
__device__ float g_attn[(size_t)B_ * S_ * D_];
__device__ float g_rsin[S_ * HALF_];
__device__ float g_rcos[S_ * HALF_];

// ---------------------------------------------------------------------------
// RoPE sin/cos table: angles[s][p] = s * theta^(-p/32)  (matches jnp fp32)
// ---------------------------------------------------------------------------
__global__ void rope_table_kernel() {
    int i = blockIdx.x * blockDim.x + threadIdx.x;
    if (i >= S_ * HALF_) return;
    int s = i >> 5;
    int p = i & 31;
    float invf = powf(10000.0f, -(float)p / 32.0f);
    float ang = (float)s * invf;
    g_rsin[i] = sinf(ang);
    g_rcos[i] = cosf(ang);
}

// ---------------------------------------------------------------------------
// SGEMM: C[m,e] = sum_d A[m,d] * W[e,d]   (M=8192, N=1024, K=1024)
// 128x128 tile, BK=8, 256 threads, 8x8 per-thread register block.
// MODE 0: plain store to C[m*1024+e]
// MODE 1: store to head layout [(b*H+h)*S+s]*64+t
// MODE 2: head layout + RoPE
// ---------------------------------------------------------------------------
template <int MODE>
__global__ __launch_bounds__(256) void gemm_kernel(const float* __restrict__ A,
                                                   const float* __restrict__ W,
                                                   float* __restrict__ C) {
    // Transposed smem tiles [BK][BM], stride 132 floats (528B = 33*16B: aligned
    // float4 rows, conflict-free scattered stores).
    __shared__ __align__(16) float As[8][132];
    __shared__ __align__(16) float Bs[8][132];

    const int tid = threadIdx.x;
    const int m0 = blockIdx.y * 128;
    const int n0 = blockIdx.x * 128;
    const int mrow = tid >> 1;          // 0..127
    const int kc = (tid & 1) << 2;      // 0 or 4
    const int ty = tid >> 4;            // 0..15
    const int tx = tid & 15;            // 0..15
    const int ty8 = ty * 8, tx8 = tx * 8;

    const float* Aptr = A + (size_t)(m0 + mrow) * D_ + kc;
    const float* Wptr = W + (size_t)(n0 + mrow) * D_ + kc;

    float acc[8][8];
#pragma unroll
    for (int i = 0; i < 8; i++)
#pragma unroll
        for (int j = 0; j < 8; j++) acc[i][j] = 0.0f;

    // register prefetch of tile 0
    float4 pa = *(const float4*)Aptr;
    float4 pb = *(const float4*)Wptr;

    const int NT = D_ / 8;  // 128 k-tiles
    for (int kt = 0; kt < NT; kt++) {
        __syncthreads();
        As[kc + 0][mrow] = pa.x; As[kc + 1][mrow] = pa.y;
        As[kc + 2][mrow] = pa.z; As[kc + 3][mrow] = pa.w;
        Bs[kc + 0][mrow] = pb.x; Bs[kc + 1][mrow] = pb.y;
        Bs[kc + 2][mrow] = pb.z; Bs[kc + 3][mrow] = pb.w;
        __syncthreads();
        if (kt + 1 < NT) {
            pa = *(const float4*)(Aptr + (kt + 1) * 8);
            pb = *(const float4*)(Wptr + (kt + 1) * 8);
        }
#pragma unroll
        for (int kk = 0; kk < 8; kk++) {
            float4 a0 = *(const float4*)&As[kk][ty8];
            float4 a1 = *(const float4*)&As[kk][ty8 + 4];
            float4 b0 = *(const float4*)&Bs[kk][tx8];
            float4 b1 = *(const float4*)&Bs[kk][tx8 + 4];
            float av[8] = {a0.x, a0.y, a0.z, a0.w, a1.x, a1.y, a1.z, a1.w};
            float bv[8] = {b0.x, b0.y, b0.z, b0.w, b1.x, b1.y, b1.z, b1.w};
#pragma unroll
            for (int i = 0; i < 8; i++)
#pragma unroll
                for (int j = 0; j < 8; j++)
                    acc[i][j] = fmaf(av[i], bv[j], acc[i][j]);
        }
    }

    const int e0 = n0 + tx8;  // 8 consecutive output cols, 8-aligned
#pragma unroll
    for (int i = 0; i < 8; i++) {
        int m = m0 + ty8 + i;
        float v[8];
#pragma unroll
        for (int j = 0; j < 8; j++) v[j] = acc[i][j];

        if (MODE == 0) {
            float4* dst = (float4*)&C[(size_t)m * D_ + e0];
            dst[0] = make_float4(v[0], v[1], v[2], v[3]);
            dst[1] = make_float4(v[4], v[5], v[6], v[7]);
        } else {
            int b = m >> 11;          // m / S_
            int s = m & (S_ - 1);
            int h = e0 >> 6;          // constant per thread (e0 8-aligned)
            int t0 = e0 & 63;
            if (MODE == 2) {
#pragma unroll
                for (int j2 = 0; j2 < 4; j2++) {
                    int p = (t0 >> 1) + j2;
                    float sn = g_rsin[s * HALF_ + p];
                    float cs = g_rcos[s * HALF_ + p];
                    float x0 = v[2 * j2], x1 = v[2 * j2 + 1];
                    v[2 * j2] = x0 * cs - x1 * sn;
                    v[2 * j2 + 1] = x0 * sn + x1 * cs;
                }
            }
            float4* dst =
                (float4*)&C[(size_t)((b * H_ + h) * S_ + s) * DK_ + t0];
            dst[0] = make_float4(v[0], v[1], v[2], v[3]);
            dst[1] = make_float4(v[4], v[5], v[6], v[7]);
        }
    }
}

// ---------------------------------------------------------------------------
// Causal flash attention, fp32. 128 queries/block (1 per thread), 64-key tiles.
// ---------------------------------------------------------------------------
__global__ __launch_bounds__(128, 2) void attn_kernel() {
    const int bh = blockIdx.y;
    const int b = bh >> 4, h = bh & 15;
    const int q0 = blockIdx.x * 128;
    const int tid = threadIdx.x;
    const int q = q0 + tid;
    const size_t head_off = (size_t)(b * H_ + h) * S_ * DK_;
    const float* Qp = g_Q + head_off;
    const float* Kp = g_K + head_off;
    const float* Vp = g_V + head_off;

    __shared__ __align__(16) float Ks[64][64];
    __shared__ __align__(16) float Vs[64][64];

    float qr[64];
#pragma unroll
    for (int i = 0; i < 16; i++) {
        float4 t = *(const float4*)&Qp[(size_t)q * DK_ + i * 4];
        qr[4 * i + 0] = t.x * SCALE_;
        qr[4 * i + 1] = t.y * SCALE_;
        qr[4 * i + 2] = t.z * SCALE_;
        qr[4 * i + 3] = t.w * SCALE_;
    }

    float mrun = -1e30f, lrun = 0.0f;
    float acc[64];
#pragma unroll
    for (int t = 0; t < 64; t++) acc[t] = 0.0f;

    const int nkb = (q0 >> 6) + 2;  // causal: key tiles 0 .. q0/64+1
    for (int kb = 0; kb < nkb; kb++) {
        __syncthreads();
#pragma unroll
        for (int i = 0; i < 8; i++) {
            int idx = i * 128 + tid;        // 1024 float4s per tile
            int r = idx >> 4;
            int c = (idx & 15) << 2;
            *(float4*)&Ks[r][c] =
                *(const float4*)&Kp[(size_t)(kb * 64 + r) * DK_ + c];
            *(float4*)&Vs[r][c] =
                *(const float4*)&Vp[(size_t)(kb * 64 + r) * DK_ + c];
        }
        __syncthreads();

        float sc[64];
        float tmax = -1e30f;
#pragma unroll
        for (int j = 0; j < 64; j++) {
            float s = 0.0f;
#pragma unroll
            for (int d = 0; d < 16; d++) {
                float4 kv = *(const float4*)&Ks[j][d * 4];  // broadcast
                s = fmaf(qr[4 * d + 0], kv.x, s);
                s = fmaf(qr[4 * d + 1], kv.y, s);
                s = fmaf(qr[4 * d + 2], kv.z, s);
                s = fmaf(qr[4 * d + 3], kv.w, s);
            }
            if (kb * 64 + j > q) s = -1e30f;  // causal mask
            sc[j] = s;
            tmax = fmaxf(tmax, s);
        }
        float mnew = fmaxf(mrun, tmax);
        float corr = __expf(mrun - mnew);
        lrun *= corr;
#pragma unroll
        for (int t = 0; t < 64; t++) acc[t] *= corr;
#pragma unroll
        for (int j = 0; j < 64; j++) {
            float p = __expf(sc[j] - mnew);
            lrun += p;
#pragma unroll
            for (int d = 0; d < 16; d++) {
                float4 vv = *(const float4*)&Vs[j][d * 4];  // broadcast
                acc[4 * d + 0] = fmaf(p, vv.x, acc[4 * d + 0]);
                acc[4 * d + 1] = fmaf(p, vv.y, acc[4 * d + 1]);
                acc[4 * d + 2] = fmaf(p, vv.z, acc[4 * d + 2]);
                acc[4 * d + 3] = fmaf(p, vv.w, acc[4 * d + 3]);
            }
        }
        mrun = mnew;
    }

    float inv = 1.0f / lrun;
    float* Op = g_attn + (size_t)(b * S_ + q) * D_ + h * DK_;
#pragma unroll
    for (int i = 0; i < 16; i++) {
        *(float4*)&Op[i * 4] =
            make_float4(acc[4 * i + 0] * inv, acc[4 * i + 1] * inv,
                        acc[4 * i + 2] * inv, acc[4 * i + 3] * inv);
    }
}

// ---------------------------------------------------------------------------
extern "C" void kernel_launch(void* const* d_in, const int* in_sizes, int n_in,
                              void* d_out, int out_size) {
    const float* x = (const float*)d_in[0];
    const float* Wq = (const float*)d_in[1];
    const float* Wk = (const float*)d_in[2];
    const float* Wv = (const float*)d_in[3];
    const float* Wo = (const float*)d_in[4];

    float *Qp, *Kp, *Vp, *Ap;
    cudaGetSymbolAddress((void**)&Qp, g_Q);
    cudaGetSymbolAddress((void**)&Kp, g_K);
    cudaGetSymbolAddress((void**)&Vp, g_V);
    cudaGetSymbolAddress((void**)&Ap, g_attn);

    rope_table_kernel<<<(S_ * HALF_ + 255) / 256, 256>>>();

    dim3 gg(D_ / 128, (B_ * S_) / 128);  // (8, 64)
    gemm_kernel<2><<<gg, 256>>>(x, Wq, Qp);
    gemm_kernel<2><<<gg, 256>>>(x, Wk, Kp);
    gemm_kernel<1><<<gg, 256>>>(x, Wv, Vp);

    attn_kernel<<<dim3(S_ / 128, B_ * H_), 128>>>();

    gemm_kernel<0><<<gg, 256>>>(Ap, Wo, (float*)d_out);
}

// round 3
// speedup vs baseline: 1.3185x; 1.3185x over previous
#include <cuda_runtime.h>
#include <cuda_bf16.h>
#include <math.h>
#include <stdint.h>

#define B_ 4
#define S_ 2048
#define D_ 1024
#define H_ 16
#define DK_ 64
#define HALF_ 32
#define SCALE_ 0.125f

// Scratch (device globals: no allocation allowed)
__device__ float g_Q[(size_t)B_ * H_ * S_ * DK_];
__device__ float g_K[(size_t)B_ * H_ * S_ * DK_];
__device__ float g_V[(size_t)B_ * H_ * S_ * DK_];
__device__ float g_attn[(size_t)B_ * S_ * D_];
__device__ float g_rsin[S_ * HALF_];
__device__ float g_rcos[S_ * HALF_];

// ---------------------------------------------------------------------------
// helpers
// ---------------------------------------------------------------------------
__device__ __forceinline__ uint32_t smem_u32(const void* p) {
    uint32_t a;
    asm("{ .reg .u64 t; cvta.to.shared.u64 t, %1; cvt.u32.u64 %0, t; }"
        : "=r"(a) : "l"(p));
    return a;
}
// pack two f32 into bf16x2 (first arg -> low half = lower memory address)
__device__ __forceinline__ uint32_t pack2(float lo, float hi) {
    uint32_t r;
    asm("cvt.rn.bf16x2.f32 %0, %1, %2;" : "=r"(r) : "f"(hi), "f"(lo));
    return r;
}
__device__ __forceinline__ float lo_f(uint32_t p) {
    return __uint_as_float(p << 16);
}
__device__ __forceinline__ float hi_f(uint32_t p) {
    return __uint_as_float(p & 0xFFFF0000u);
}
#define SW128(o) ((o) ^ (((o) >> 3) & 0x70))

__device__ __forceinline__ void ldm4(uint32_t* r, uint32_t addr) {
    asm volatile(
        "ldmatrix.sync.aligned.m8n8.x4.shared.b16 {%0,%1,%2,%3}, [%4];"
        : "=r"(r[0]), "=r"(r[1]), "=r"(r[2]), "=r"(r[3]) : "r"(addr));
}
__device__ __forceinline__ void mma_bf16(float* d, const uint32_t* a,
                                         const uint32_t* b) {
    asm volatile(
        "mma.sync.aligned.m16n8k16.row.col.f32.bf16.bf16.f32 "
        "{%0,%1,%2,%3},{%4,%5,%6,%7},{%8,%9},{%0,%1,%2,%3};"
        : "+f"(d[0]), "+f"(d[1]), "+f"(d[2]), "+f"(d[3])
        : "r"(a[0]), "r"(a[1]), "r"(a[2]), "r"(a[3]), "r"(b[0]), "r"(b[1]));
}

// ---------------------------------------------------------------------------
// RoPE sin/cos table: angles[s][p] = s * theta^(-p/32)
// ---------------------------------------------------------------------------
__global__ void rope_table_kernel() {
    int i = blockIdx.x * blockDim.x + threadIdx.x;
    if (i >= S_ * HALF_) return;
    int s = i >> 5;
    int p = i & 31;
    float invf = powf(10000.0f, -(float)p / 32.0f);
    float ang = (float)s * invf;
    g_rsin[i] = sinf(ang);
    g_rcos[i] = cosf(ang);
}

// ---------------------------------------------------------------------------
// HMMA bf16-split GEMM: C[m,e] = sum_d A[m,d] * W[e,d]   (M=8192, N=K=1024)
// CTA tile 128x128, K-chunk 64; 512 threads = 16 warps of 32x32 warp tiles.
// fp32 split: a = hi + lo (bf16); D += Ah*Bh + Ah*Bl + Al*Bh  (fp32 accum).
// smem per operand-half: 128 rows x 128B (SW128 swizzled) = 16KB; total 64KB.
// MODE 0: C[m*1024+e]; MODE 1: head scatter; MODE 2: head scatter + RoPE.
// ---------------------------------------------------------------------------
#define GEMM_SMEM 65536

template <int MODE>
__global__ __launch_bounds__(512) void hmma_gemm(const float* __restrict__ A,
                                                 const float* __restrict__ W,
                                                 float* __restrict__ C) {
    extern __shared__ char smem[];
    const uint32_t sb = smem_u32(smem);
    const int tid = threadIdx.x;
    const int wid = tid >> 5;
    const int lane = tid & 31;
    const int m0 = blockIdx.y * 128;
    const int n0 = blockIdx.x * 128;
    const int wm = (wid & 3) * 32;   // warp m offset in tile
    const int wn = (wid >> 2) * 32;  // warp n offset in tile

    // per-thread gmem load pattern: 4 float4 per operand per chunk
    const int rr = tid >> 4;   // 0..31 (row within group of 32)
    const int c4 = tid & 15;   // float4 column

    float acc[2][4][4];
#pragma unroll
    for (int mt = 0; mt < 2; mt++)
#pragma unroll
        for (int nt = 0; nt < 4; nt++)
#pragma unroll
            for (int i = 0; i < 4; i++) acc[mt][nt][i] = 0.0f;

    const float* Ab = A + (size_t)m0 * D_;
    const float* Wb = W + (size_t)n0 * D_;

    float4 pa[4], pb[4];
#pragma unroll
    for (int it = 0; it < 4; it++) {
        pa[it] = *(const float4*)(Ab + (size_t)(it * 32 + rr) * D_ + c4 * 4);
        pb[it] = *(const float4*)(Wb + (size_t)(it * 32 + rr) * D_ + c4 * 4);
    }

    for (int ch = 0; ch < 16; ch++) {
        __syncthreads();
        // convert + split + store to swizzled smem
#pragma unroll
        for (int it = 0; it < 4; it++) {
            int r = it * 32 + rr;
            uint32_t off = SW128((uint32_t)(r * 128 + c4 * 8));
            float4 v = pa[it];
            uint32_t h0 = pack2(v.x, v.y), h1 = pack2(v.z, v.w);
            uint32_t l0 = pack2(v.x - lo_f(h0), v.y - hi_f(h0));
            uint32_t l1 = pack2(v.z - lo_f(h1), v.w - hi_f(h1));
            *(uint2*)(smem + off) = make_uint2(h0, h1);
            *(uint2*)(smem + 16384 + off) = make_uint2(l0, l1);
            v = pb[it];
            h0 = pack2(v.x, v.y); h1 = pack2(v.z, v.w);
            l0 = pack2(v.x - lo_f(h0), v.y - hi_f(h0));
            l1 = pack2(v.z - lo_f(h1), v.w - hi_f(h1));
            *(uint2*)(smem + 32768 + off) = make_uint2(h0, h1);
            *(uint2*)(smem + 49152 + off) = make_uint2(l0, l1);
        }
        __syncthreads();

        if (ch < 15) {
#pragma unroll
            for (int it = 0; it < 4; it++) {
                pa[it] = *(const float4*)(Ab + (size_t)(it * 32 + rr) * D_ +
                                          (ch + 1) * 64 + c4 * 4);
                pb[it] = *(const float4*)(Wb + (size_t)(it * 32 + rr) * D_ +
                                          (ch + 1) * 64 + c4 * 4);
            }
        }

#pragma unroll
        for (int ks = 0; ks < 4; ks++) {
            const int k0 = ks * 16;
            uint32_t ah[2][4], al[2][4], bh[2][4], bl[2][4];
#pragma unroll
            for (int mt = 0; mt < 2; mt++) {
                int row = wm + mt * 16 + (lane & 15);
                int kc = k0 + ((lane >> 4) << 3);
                uint32_t addr =
                    sb + row * 128 + ((((kc >> 3) ^ (row & 7)) << 4));
                ldm4(ah[mt], addr);
                ldm4(al[mt], addr + 16384);
            }
#pragma unroll
            for (int bt = 0; bt < 2; bt++) {
                int row = wn + bt * 16 + ((lane >> 4) << 3) + (lane & 7);
                int kc = k0 + (((lane >> 3) & 1) << 3);
                uint32_t addr = sb + 32768 + row * 128 +
                                ((((kc >> 3) ^ (row & 7)) << 4));
                ldm4(bh[bt], addr);
                ldm4(bl[bt], addr + 16384);
            }
#pragma unroll
            for (int mt = 0; mt < 2; mt++)
#pragma unroll
                for (int nt = 0; nt < 4; nt++) {
                    const uint32_t* ph = &bh[nt >> 1][(nt & 1) * 2];
                    const uint32_t* pl = &bl[nt >> 1][(nt & 1) * 2];
                    mma_bf16(acc[mt][nt], ah[mt], ph);
                    mma_bf16(acc[mt][nt], ah[mt], pl);
                    mma_bf16(acc[mt][nt], al[mt], ph);
                }
        }
    }

    // -------- epilogue (accum layout: d0:(r,c) d1:(r,c+1) d2:(r+8,c) d3) ----
    const int rbase = m0 + wm + (lane >> 2);
    const int cbase = n0 + wn + (lane & 3) * 2;
#pragma unroll
    for (int mt = 0; mt < 2; mt++) {
#pragma unroll
        for (int half = 0; half < 2; half++) {
            const int m = rbase + mt * 16 + half * 8;
#pragma unroll
            for (int nt = 0; nt < 4; nt++) {
                float v0 = acc[mt][nt][half * 2 + 0];
                float v1 = acc[mt][nt][half * 2 + 1];
                const int col = cbase + nt * 8;
                if (MODE == 0) {
                    *(float2*)(C + (size_t)m * D_ + col) =
                        make_float2(v0, v1);
                } else {
                    const int b = m >> 11;
                    const int s = m & (S_ - 1);
                    const int h = col >> 6;
                    const int t = col & 63;
                    if (MODE == 2) {
                        int p = t >> 1;
                        float sn = g_rsin[s * HALF_ + p];
                        float cs = g_rcos[s * HALF_ + p];
                        float x0 = v0, x1 = v1;
                        v0 = x0 * cs - x1 * sn;
                        v1 = x0 * sn + x1 * cs;
                    }
                    *(float2*)(C + (size_t)((b * H_ + h) * S_ + s) * DK_ + t) =
                        make_float2(v0, v1);
                }
            }
        }
    }
}

// ---------------------------------------------------------------------------
// Causal flash attention, fp32. 128 queries/block (1 per thread), 64-key tiles.
// 4-way partial score accumulation (breaks the serial FMA chain).
// ---------------------------------------------------------------------------
__global__ __launch_bounds__(128, 2) void attn_kernel() {
    const int bh = blockIdx.y;
    const int b = bh >> 4, h = bh & 15;
    const int q0 = blockIdx.x * 128;
    const int tid = threadIdx.x;
    const int q = q0 + tid;
    const size_t head_off = (size_t)(b * H_ + h) * S_ * DK_;
    const float* Qp = g_Q + head_off;
    const float* Kp = g_K + head_off;
    const float* Vp = g_V + head_off;

    __shared__ __align__(16) float Ks[64][64];
    __shared__ __align__(16) float Vs[64][64];

    float qr[64];
#pragma unroll
    for (int i = 0; i < 16; i++) {
        float4 t = *(const float4*)&Qp[(size_t)q * DK_ + i * 4];
        qr[4 * i + 0] = t.x * SCALE_;
        qr[4 * i + 1] = t.y * SCALE_;
        qr[4 * i + 2] = t.z * SCALE_;
        qr[4 * i + 3] = t.w * SCALE_;
    }

    float mrun = -1e30f, lrun = 0.0f;
    float acc[64];
#pragma unroll
    for (int t = 0; t < 64; t++) acc[t] = 0.0f;

    const int fullkb = q0 >> 6;  // tiles fully below the diagonal
    const int nkb = fullkb + 2;
    for (int kb = 0; kb < nkb; kb++) {
        __syncthreads();
#pragma unroll
        for (int i = 0; i < 8; i++) {
            int idx = i * 128 + tid;
            int r = idx >> 4;
            int c = (idx & 15) << 2;
            *(float4*)&Ks[r][c] =
                *(const float4*)&Kp[(size_t)(kb * 64 + r) * DK_ + c];
            *(float4*)&Vs[r][c] =
                *(const float4*)&Vp[(size_t)(kb * 64 + r) * DK_ + c];
        }
        __syncthreads();

        const bool masked = (kb >= fullkb);  // block-uniform branch
        float sc[64];
        float tmax = -1e30f;
#pragma unroll
        for (int j = 0; j < 64; j++) {
            float s0 = 0.0f, s1 = 0.0f, s2 = 0.0f, s3 = 0.0f;
#pragma unroll
            for (int d = 0; d < 16; d++) {
                float4 kv = *(const float4*)&Ks[j][d * 4];  // broadcast
                s0 = fmaf(qr[4 * d + 0], kv.x, s0);
                s1 = fmaf(qr[4 * d + 1], kv.y, s1);
                s2 = fmaf(qr[4 * d + 2], kv.z, s2);
                s3 = fmaf(qr[4 * d + 3], kv.w, s3);
            }
            float s = (s0 + s1) + (s2 + s3);
            if (masked && (kb * 64 + j > q)) s = -1e30f;
            sc[j] = s;
            tmax = fmaxf(tmax, s);
        }
        float mnew = fmaxf(mrun, tmax);
        float corr = __expf(mrun - mnew);
        lrun *= corr;
#pragma unroll
        for (int t = 0; t < 64; t++) acc[t] *= corr;
#pragma unroll
        for (int j = 0; j < 64; j++) {
            float p = __expf(sc[j] - mnew);
            lrun += p;
#pragma unroll
            for (int d = 0; d < 16; d++) {
                float4 vv = *(const float4*)&Vs[j][d * 4];  // broadcast
                acc[4 * d + 0] = fmaf(p, vv.x, acc[4 * d + 0]);
                acc[4 * d + 1] = fmaf(p, vv.y, acc[4 * d + 1]);
                acc[4 * d + 2] = fmaf(p, vv.z, acc[4 * d + 2]);
                acc[4 * d + 3] = fmaf(p, vv.w, acc[4 * d + 3]);
            }
        }
        mrun = mnew;
    }

    float inv = 1.0f / lrun;
    float* Op = g_attn + (size_t)(b * S_ + q) * D_ + h * DK_;
#pragma unroll
    for (int i = 0; i < 16; i++) {
        *(float4*)&Op[i * 4] =
            make_float4(acc[4 * i + 0] * inv, acc[4 * i + 1] * inv,
                        acc[4 * i + 2] * inv, acc[4 * i + 3] * inv);
    }
}

// ---------------------------------------------------------------------------
extern "C" void kernel_launch(void* const* d_in, const int* in_sizes, int n_in,
                              void* d_out, int out_size) {
    const float* x = (const float*)d_in[0];
    const float* Wq = (const float*)d_in[1];
    const float* Wk = (const float*)d_in[2];
    const float* Wv = (const float*)d_in[3];
    const float* Wo = (const float*)d_in[4];

    float *Qp, *Kp, *Vp, *Ap;
    cudaGetSymbolAddress((void**)&Qp, g_Q);
    cudaGetSymbolAddress((void**)&Kp, g_K);
    cudaGetSymbolAddress((void**)&Vp, g_V);
    cudaGetSymbolAddress((void**)&Ap, g_attn);

    cudaFuncSetAttribute(hmma_gemm<0>,
                         cudaFuncAttributeMaxDynamicSharedMemorySize, GEMM_SMEM);
    cudaFuncSetAttribute(hmma_gemm<1>,
                         cudaFuncAttributeMaxDynamicSharedMemorySize, GEMM_SMEM);
    cudaFuncSetAttribute(hmma_gemm<2>,
                         cudaFuncAttributeMaxDynamicSharedMemorySize, GEMM_SMEM);

    rope_table_kernel<<<(S_ * HALF_ + 255) / 256, 256>>>();

    dim3 gg(D_ / 128, (B_ * S_) / 128);  // (8, 64)
    hmma_gemm<2><<<gg, 512, GEMM_SMEM>>>(x, Wq, Qp);
    hmma_gemm<2><<<gg, 512, GEMM_SMEM>>>(x, Wk, Kp);
    hmma_gemm<1><<<gg, 512, GEMM_SMEM>>>(x, Wv, Vp);

    attn_kernel<<<dim3(S_ / 128, B_ * H_), 128>>>();

    hmma_gemm<0><<<gg, 512, GEMM_SMEM>>>(Ap, Wo, (float*)d_out);
}

// round 5
// speedup vs baseline: 4.4247x; 3.3558x over previous
#include <cuda_runtime.h>
#include <cuda_bf16.h>
#include <math.h>
#include <stdint.h>

#define B_ 4
#define S_ 2048
#define D_ 1024
#define H_ 16
#define DK_ 64
#define HALF_ 32
#define SCALE_ 0.125f

// Scratch (device globals: no allocation allowed)
__device__ float g_Q[(size_t)B_ * H_ * S_ * DK_];
__device__ float g_K[(size_t)B_ * H_ * S_ * DK_];
__device__ float g_V[(size_t)B_ * H_ * S_ * DK_];
__device__ float g_attn[(size_t)B_ * S_ * D_];
__device__ float g_rsin[S_ * HALF_];
__device__ float g_rcos[S_ * HALF_];

// ---------------------------------------------------------------------------
// helpers
// ---------------------------------------------------------------------------
__device__ __forceinline__ uint32_t smem_u32(const void* p) {
    uint32_t a;
    asm("{ .reg .u64 t; cvta.to.shared.u64 t, %1; cvt.u32.u64 %0, t; }"
        : "=r"(a) : "l"(p));
    return a;
}
// pack two f32 into bf16x2 (first arg -> low half = lower memory address)
__device__ __forceinline__ uint32_t pack2(float lo, float hi) {
    uint32_t r;
    asm("cvt.rn.bf16x2.f32 %0, %1, %2;" : "=r"(r) : "f"(hi), "f"(lo));
    return r;
}
__device__ __forceinline__ float lo_f(uint32_t p) {
    return __uint_as_float(p << 16);
}
__device__ __forceinline__ float hi_f(uint32_t p) {
    return __uint_as_float(p & 0xFFFF0000u);
}
#define SW128(o) ((o) ^ (((o) >> 3) & 0x70))

__device__ __forceinline__ void ldm4(uint32_t* r, uint32_t addr) {
    asm volatile(
        "ldmatrix.sync.aligned.m8n8.x4.shared.b16 {%0,%1,%2,%3}, [%4];"
        : "=r"(r[0]), "=r"(r[1]), "=r"(r[2]), "=r"(r[3]) : "r"(addr));
}
__device__ __forceinline__ void ldm4t(uint32_t* r, uint32_t addr) {
    asm volatile(
        "ldmatrix.sync.aligned.m8n8.x4.trans.shared.b16 {%0,%1,%2,%3}, [%4];"
        : "=r"(r[0]), "=r"(r[1]), "=r"(r[2]), "=r"(r[3]) : "r"(addr));
}
__device__ __forceinline__ void mma_bf16(float* d, const uint32_t* a,
                                         const uint32_t* b) {
    asm volatile(
        "mma.sync.aligned.m16n8k16.row.col.f32.bf16.bf16.f32 "
        "{%0,%1,%2,%3},{%4,%5,%6,%7},{%8,%9},{%0,%1,%2,%3};"
        : "+f"(d[0]), "+f"(d[1]), "+f"(d[2]), "+f"(d[3])
        : "r"(a[0]), "r"(a[1]), "r"(a[2]), "r"(a[3]), "r"(b[0]), "r"(b[1]));
}

// ---------------------------------------------------------------------------
// RoPE sin/cos table: angles[s][p] = s * theta^(-p/32)
// ---------------------------------------------------------------------------
__global__ void rope_table_kernel() {
    int i = blockIdx.x * blockDim.x + threadIdx.x;
    if (i >= S_ * HALF_) return;
    int s = i >> 5;
    int p = i & 31;
    float invf = powf(10000.0f, -(float)p / 32.0f);
    float ang = (float)s * invf;
    g_rsin[i] = sinf(ang);
    g_rcos[i] = cosf(ang);
}

// ---------------------------------------------------------------------------
// HMMA bf16-split GEMM (unchanged from R3; 153us/launch, tensor=55%)
// ---------------------------------------------------------------------------
#define GEMM_SMEM 65536

template <int MODE>
__global__ __launch_bounds__(512) void hmma_gemm(const float* __restrict__ A,
                                                 const float* __restrict__ W,
                                                 float* __restrict__ C) {
    extern __shared__ char smem[];
    const uint32_t sb = smem_u32(smem);
    const int tid = threadIdx.x;
    const int wid = tid >> 5;
    const int lane = tid & 31;
    const int m0 = blockIdx.y * 128;
    const int n0 = blockIdx.x * 128;
    const int wm = (wid & 3) * 32;
    const int wn = (wid >> 2) * 32;

    const int rr = tid >> 4;
    const int c4 = tid & 15;

    float acc[2][4][4];
#pragma unroll
    for (int mt = 0; mt < 2; mt++)
#pragma unroll
        for (int nt = 0; nt < 4; nt++)
#pragma unroll
            for (int i = 0; i < 4; i++) acc[mt][nt][i] = 0.0f;

    const float* Ab = A + (size_t)m0 * D_;
    const float* Wb = W + (size_t)n0 * D_;

    float4 pa[4], pb[4];
#pragma unroll
    for (int it = 0; it < 4; it++) {
        pa[it] = *(const float4*)(Ab + (size_t)(it * 32 + rr) * D_ + c4 * 4);
        pb[it] = *(const float4*)(Wb + (size_t)(it * 32 + rr) * D_ + c4 * 4);
    }

    for (int ch = 0; ch < 16; ch++) {
        __syncthreads();
#pragma unroll
        for (int it = 0; it < 4; it++) {
            int r = it * 32 + rr;
            uint32_t off = SW128((uint32_t)(r * 128 + c4 * 8));
            float4 v = pa[it];
            uint32_t h0 = pack2(v.x, v.y), h1 = pack2(v.z, v.w);
            uint32_t l0 = pack2(v.x - lo_f(h0), v.y - hi_f(h0));
            uint32_t l1 = pack2(v.z - lo_f(h1), v.w - hi_f(h1));
            *(uint2*)(smem + off) = make_uint2(h0, h1);
            *(uint2*)(smem + 16384 + off) = make_uint2(l0, l1);
            v = pb[it];
            h0 = pack2(v.x, v.y); h1 = pack2(v.z, v.w);
            l0 = pack2(v.x - lo_f(h0), v.y - hi_f(h0));
            l1 = pack2(v.z - lo_f(h1), v.w - hi_f(h1));
            *(uint2*)(smem + 32768 + off) = make_uint2(h0, h1);
            *(uint2*)(smem + 49152 + off) = make_uint2(l0, l1);
        }
        __syncthreads();

        if (ch < 15) {
#pragma unroll
            for (int it = 0; it < 4; it++) {
                pa[it] = *(const float4*)(Ab + (size_t)(it * 32 + rr) * D_ +
                                          (ch + 1) * 64 + c4 * 4);
                pb[it] = *(const float4*)(Wb + (size_t)(it * 32 + rr) * D_ +
                                          (ch + 1) * 64 + c4 * 4);
            }
        }

#pragma unroll
        for (int ks = 0; ks < 4; ks++) {
            const int k0 = ks * 16;
            uint32_t ah[2][4], al[2][4], bh[2][4], bl[2][4];
#pragma unroll
            for (int mt = 0; mt < 2; mt++) {
                int row = wm + mt * 16 + (lane & 15);
                int kc = k0 + ((lane >> 4) << 3);
                uint32_t addr =
                    sb + row * 128 + ((((kc >> 3) ^ (row & 7)) << 4));
                ldm4(ah[mt], addr);
                ldm4(al[mt], addr + 16384);
            }
#pragma unroll
            for (int bt = 0; bt < 2; bt++) {
                int row = wn + bt * 16 + ((lane >> 4) << 3) + (lane & 7);
                int kc = k0 + (((lane >> 3) & 1) << 3);
                uint32_t addr = sb + 32768 + row * 128 +
                                ((((kc >> 3) ^ (row & 7)) << 4));
                ldm4(bh[bt], addr);
                ldm4(bl[bt], addr + 16384);
            }
#pragma unroll
            for (int mt = 0; mt < 2; mt++)
#pragma unroll
                for (int nt = 0; nt < 4; nt++) {
                    const uint32_t* ph = &bh[nt >> 1][(nt & 1) * 2];
                    const uint32_t* pl = &bl[nt >> 1][(nt & 1) * 2];
                    mma_bf16(acc[mt][nt], ah[mt], ph);
                    mma_bf16(acc[mt][nt], ah[mt], pl);
                    mma_bf16(acc[mt][nt], al[mt], ph);
                }
        }
    }

    const int rbase = m0 + wm + (lane >> 2);
    const int cbase = n0 + wn + (lane & 3) * 2;
#pragma unroll
    for (int mt = 0; mt < 2; mt++) {
#pragma unroll
        for (int half = 0; half < 2; half++) {
            const int m = rbase + mt * 16 + half * 8;
#pragma unroll
            for (int nt = 0; nt < 4; nt++) {
                float v0 = acc[mt][nt][half * 2 + 0];
                float v1 = acc[mt][nt][half * 2 + 1];
                const int col = cbase + nt * 8;
                if (MODE == 0) {
                    *(float2*)(C + (size_t)m * D_ + col) =
                        make_float2(v0, v1);
                } else {
                    const int b = m >> 11;
                    const int s = m & (S_ - 1);
                    const int h = col >> 6;
                    const int t = col & 63;
                    if (MODE == 2) {
                        int p = t >> 1;
                        float sn = g_rsin[s * HALF_ + p];
                        float cs = g_rcos[s * HALF_ + p];
                        float x0 = v0, x1 = v1;
                        v0 = x0 * cs - x1 * sn;
                        v1 = x0 * sn + x1 * cs;
                    }
                    *(float2*)(C + (size_t)((b * H_ + h) * S_ + s) * DK_ + t) =
                        make_float2(v0, v1);
                }
            }
        }
    }
}

// ---------------------------------------------------------------------------
// HMMA flash attention, bf16-split everywhere (err ~1e-5).
// CTA = (64-q-block, b*H+h); 4 warps x 16 q rows; 64-key K/V tiles.
// ---------------------------------------------------------------------------
__global__ __launch_bounds__(128) void attn_mma_kernel() {
    const int bh = blockIdx.y;
    const int b = bh >> 4, h = bh & 15;
    const int qb = blockIdx.x;
    const int tid = threadIdx.x;
    const int wid = tid >> 5;
    const int lane = tid & 31;

    const size_t head_off = (size_t)bh * S_ * DK_;
    const float* Qp = g_Q + head_off + (size_t)qb * 64 * DK_;
    const float* Kp = g_K + head_off;
    const float* Vp = g_V + head_off;

    __shared__ __align__(16) char sm[32768];
    const uint32_t sKh = smem_u32(sm);
    const uint32_t sVh = sKh + 16384;

    // ---- stage Q (scaled) into Kh/Kl region, pull A-fragments to regs ----
    // 64 rows x 16 float4/row = 1024 float4s -> 8 iterations of 128 threads
#pragma unroll
    for (int it = 0; it < 8; it++) {
        int idx = it * 128 + tid;
        int r = idx >> 4, c4 = idx & 15;
        float4 v = *(const float4*)(Qp + (size_t)r * DK_ + c4 * 4);
        v.x *= SCALE_; v.y *= SCALE_; v.z *= SCALE_; v.w *= SCALE_;
        uint32_t h0 = pack2(v.x, v.y), h1 = pack2(v.z, v.w);
        uint32_t l0 = pack2(v.x - lo_f(h0), v.y - hi_f(h0));
        uint32_t l1 = pack2(v.z - lo_f(h1), v.w - hi_f(h1));
        uint32_t off = (uint32_t)(r * 128) + (((uint32_t)(c4 * 8)) ^
                                             (((uint32_t)(r & 7)) << 4));
        *(uint2*)(sm + off) = make_uint2(h0, h1);
        *(uint2*)(sm + 8192 + off) = make_uint2(l0, l1);
    }
    __syncthreads();

    uint32_t qh[4][4], ql[4][4];
#pragma unroll
    for (int kk = 0; kk < 4; kk++) {
        int row = wid * 16 + (lane & 15);
        int kbyte = kk * 32 + ((lane >> 4) << 4);
        uint32_t ad =
            sKh + row * 128 + (((uint32_t)kbyte) ^ (((uint32_t)(row & 7)) << 4));
        ldm4(qh[kk], ad);
        ldm4(ql[kk], ad + 8192);
    }
    __syncthreads();

    float oacc[8][4];
#pragma unroll
    for (int j = 0; j < 8; j++)
#pragma unroll
        for (int i = 0; i < 4; i++) oacc[j][i] = 0.0f;
    float m1 = -1e30f, m2 = -1e30f, l1 = 0.0f, l2 = 0.0f;

    for (int kb = 0; kb <= qb; kb++) {
        // ---- load K/V tile, split to bf16 hi/lo smem ----
#pragma unroll
        for (int it = 0; it < 8; it++) {
            int idx = it * 128 + tid;
            int r = idx >> 4, c4 = idx & 15;
            uint32_t off = (uint32_t)(r * 128) + (((uint32_t)(c4 * 8)) ^
                                                 (((uint32_t)(r & 7)) << 4));
            float4 v = *(const float4*)(Kp + (size_t)(kb * 64 + r) * DK_ +
                                        c4 * 4);
            uint32_t h0 = pack2(v.x, v.y), h1 = pack2(v.z, v.w);
            uint32_t l0 = pack2(v.x - lo_f(h0), v.y - hi_f(h0));
            uint32_t l1v = pack2(v.z - lo_f(h1), v.w - hi_f(h1));
            *(uint2*)(sm + off) = make_uint2(h0, h1);
            *(uint2*)(sm + 8192 + off) = make_uint2(l0, l1v);
            v = *(const float4*)(Vp + (size_t)(kb * 64 + r) * DK_ + c4 * 4);
            h0 = pack2(v.x, v.y); h1 = pack2(v.z, v.w);
            l0 = pack2(v.x - lo_f(h0), v.y - hi_f(h0));
            l1v = pack2(v.z - lo_f(h1), v.w - hi_f(h1));
            *(uint2*)(sm + 16384 + off) = make_uint2(h0, h1);
            *(uint2*)(sm + 24576 + off) = make_uint2(l0, l1v);
        }
        __syncthreads();

        // ---- S = Q K^T (split 3-mma) ----
        float sacc[8][4];
#pragma unroll
        for (int j = 0; j < 8; j++)
#pragma unroll
            for (int i = 0; i < 4; i++) sacc[j][i] = 0.0f;

#pragma unroll
        for (int kt = 0; kt < 4; kt++) {
#pragma unroll
            for (int kk = 0; kk < 4; kk++) {
                uint32_t khf[4], klf[4];
                int row = kt * 16 + ((lane >> 4) << 3) + (lane & 7);
                int kbyte = kk * 32 + (((lane >> 3) & 1) << 4);
                uint32_t ad = sKh + row * 128 +
                              (((uint32_t)kbyte) ^
                               (((uint32_t)(row & 7)) << 4));
                ldm4(khf, ad);
                ldm4(klf, ad + 8192);
#pragma unroll
                for (int sub = 0; sub < 2; sub++) {
                    int j = kt * 2 + sub;
                    mma_bf16(sacc[j], qh[kk], &khf[sub * 2]);
                    mma_bf16(sacc[j], qh[kk], &klf[sub * 2]);
                    mma_bf16(sacc[j], ql[kk], &khf[sub * 2]);
                }
            }
        }

        // ---- causal mask (diagonal tile only) ----
        const int rq1 = qb * 64 + wid * 16 + (lane >> 2);
        const int rq2 = rq1 + 8;
        if (kb == qb) {
            const int cb = kb * 64 + (lane & 3) * 2;
#pragma unroll
            for (int j = 0; j < 8; j++) {
#pragma unroll
                for (int e = 0; e < 2; e++) {
                    int col = cb + j * 8 + e;
                    if (col > rq1) sacc[j][e] = -1e30f;
                    if (col > rq2) sacc[j][2 + e] = -1e30f;
                }
            }
        }

        // ---- online softmax (fragment layout) ----
        float mx1 = -1e30f, mx2 = -1e30f;
#pragma unroll
        for (int j = 0; j < 8; j++) {
            mx1 = fmaxf(mx1, fmaxf(sacc[j][0], sacc[j][1]));
            mx2 = fmaxf(mx2, fmaxf(sacc[j][2], sacc[j][3]));
        }
        mx1 = fmaxf(mx1, __shfl_xor_sync(0xFFFFFFFFu, mx1, 1));
        mx1 = fmaxf(mx1, __shfl_xor_sync(0xFFFFFFFFu, mx1, 2));
        mx2 = fmaxf(mx2, __shfl_xor_sync(0xFFFFFFFFu, mx2, 1));
        mx2 = fmaxf(mx2, __shfl_xor_sync(0xFFFFFFFFu, mx2, 2));
        float mn1 = fmaxf(m1, mx1);
        float mn2 = fmaxf(m2, mx2);
        float cor1 = __expf(m1 - mn1);
        float cor2 = __expf(m2 - mn2);
        m1 = mn1; m2 = mn2;
        float sum1 = 0.0f, sum2 = 0.0f;
#pragma unroll
        for (int j = 0; j < 8; j++) {
            sacc[j][0] = __expf(sacc[j][0] - mn1);
            sacc[j][1] = __expf(sacc[j][1] - mn1);
            sacc[j][2] = __expf(sacc[j][2] - mn2);
            sacc[j][3] = __expf(sacc[j][3] - mn2);
            sum1 += sacc[j][0] + sacc[j][1];
            sum2 += sacc[j][2] + sacc[j][3];
        }
        sum1 += __shfl_xor_sync(0xFFFFFFFFu, sum1, 1);
        sum1 += __shfl_xor_sync(0xFFFFFFFFu, sum1, 2);
        sum2 += __shfl_xor_sync(0xFFFFFFFFu, sum2, 1);
        sum2 += __shfl_xor_sync(0xFFFFFFFFu, sum2, 2);
        l1 = l1 * cor1 + sum1;
        l2 = l2 * cor2 + sum2;
#pragma unroll
        for (int j = 0; j < 8; j++) {
            oacc[j][0] *= cor1; oacc[j][1] *= cor1;
            oacc[j][2] *= cor2; oacc[j][3] *= cor2;
        }

        // ---- O += P V  (P re-packed in-register, split 3-mma) ----
#pragma unroll
        for (int kk = 0; kk < 4; kk++) {
            uint32_t aPh[4], aPl[4];
            {
                const float* p0 = sacc[2 * kk];
                const float* p1 = sacc[2 * kk + 1];
                aPh[0] = pack2(p0[0], p0[1]);
                aPh[1] = pack2(p0[2], p0[3]);
                aPh[2] = pack2(p1[0], p1[1]);
                aPh[3] = pack2(p1[2], p1[3]);
                aPl[0] = pack2(p0[0] - lo_f(aPh[0]), p0[1] - hi_f(aPh[0]));
                aPl[1] = pack2(p0[2] - lo_f(aPh[1]), p0[3] - hi_f(aPh[1]));
                aPl[2] = pack2(p1[0] - lo_f(aPh[2]), p1[1] - hi_f(aPh[2]));
                aPl[3] = pack2(p1[2] - lo_f(aPh[3]), p1[3] - hi_f(aPh[3]));
            }
#pragma unroll
            for (int pr = 0; pr < 4; pr++) {
                uint32_t vhf[4], vlf[4];
                int key = kk * 16 + (((lane >> 3) & 1) << 3) + (lane & 7);
                int dbyte = pr * 32 + ((lane >> 4) << 4);
                uint32_t ad = sVh + key * 128 +
                              (((uint32_t)dbyte) ^
                               (((uint32_t)(key & 7)) << 4));
                ldm4t(vhf, ad);
                ldm4t(vlf, ad + 8192);
#pragma unroll
                for (int sub = 0; sub < 2; sub++) {
                    int j = pr * 2 + sub;
                    mma_bf16(oacc[j], aPh, &vhf[sub * 2]);
                    mma_bf16(oacc[j], aPh, &vlf[sub * 2]);
                    mma_bf16(oacc[j], aPl, &vhf[sub * 2]);
                }
            }
        }
        __syncthreads();
    }

    // ---- write O / l to g_attn [b][s][h*64+d] ----
    const float inv1 = 1.0f / l1;
    const float inv2 = 1.0f / l2;
    const int rq1 = qb * 64 + wid * 16 + (lane >> 2);
    const int rq2 = rq1 + 8;
    float* O1 = g_attn + (size_t)(b * S_ + rq1) * D_ + h * DK_;
    float* O2 = g_attn + (size_t)(b * S_ + rq2) * D_ + h * DK_;
#pragma unroll
    for (int j = 0; j < 8; j++) {
        int col = j * 8 + (lane & 3) * 2;
        *(float2*)(O1 + col) =
            make_float2(oacc[j][0] * inv1, oacc[j][1] * inv1);
        *(float2*)(O2 + col) =
            make_float2(oacc[j][2] * inv2, oacc[j][3] * inv2);
    }
}

// ---------------------------------------------------------------------------
extern "C" void kernel_launch(void* const* d_in, const int* in_sizes, int n_in,
                              void* d_out, int out_size) {
    const float* x = (const float*)d_in[0];
    const float* Wq = (const float*)d_in[1];
    const float* Wk = (const float*)d_in[2];
    const float* Wv = (const float*)d_in[3];
    const float* Wo = (const float*)d_in[4];

    float *Qp, *Kp, *Vp, *Ap;
    cudaGetSymbolAddress((void**)&Qp, g_Q);
    cudaGetSymbolAddress((void**)&Kp, g_K);
    cudaGetSymbolAddress((void**)&Vp, g_V);
    cudaGetSymbolAddress((void**)&Ap, g_attn);

    cudaFuncSetAttribute(hmma_gemm<0>,
                         cudaFuncAttributeMaxDynamicSharedMemorySize, GEMM_SMEM);
    cudaFuncSetAttribute(hmma_gemm<1>,
                         cudaFuncAttributeMaxDynamicSharedMemorySize, GEMM_SMEM);
    cudaFuncSetAttribute(hmma_gemm<2>,
                         cudaFuncAttributeMaxDynamicSharedMemorySize, GEMM_SMEM);

    rope_table_kernel<<<(S_ * HALF_ + 255) / 256, 256>>>();

    dim3 gg(D_ / 128, (B_ * S_) / 128);  // (8, 64)
    hmma_gemm<2><<<gg, 512, GEMM_SMEM>>>(x, Wq, Qp);
    hmma_gemm<2><<<gg, 512, GEMM_SMEM>>>(x, Wk, Kp);
    hmma_gemm<1><<<gg, 512, GEMM_SMEM>>>(x, Wv, Vp);

    attn_mma_kernel<<<dim3(S_ / 64, B_ * H_), 128>>>();

    hmma_gemm<0><<<gg, 512, GEMM_SMEM>>>(Ap, Wo, (float*)d_out);
}

// round 6
// speedup vs baseline: 4.4703x; 1.0103x over previous
#include <cuda_runtime.h>
#include <cuda_bf16.h>
#include <math.h>
#include <stdint.h>

#define B_ 4
#define S_ 2048
#define D_ 1024
#define H_ 16
#define DK_ 64
#define HALF_ 32
#define SCALE_ 0.125f

typedef __nv_bfloat16 bf16;

// ---------------------------------------------------------------------------
// Scratch (device globals: no allocation allowed)
// ---------------------------------------------------------------------------
__device__ bf16 g_xh[(size_t)8192 * 1024], g_xl[(size_t)8192 * 1024];
__device__ bf16 g_Wch[(size_t)3072 * 1024], g_Wcl[(size_t)3072 * 1024];
__device__ bf16 g_Woh[(size_t)1024 * 1024], g_Wol[(size_t)1024 * 1024];
__device__ bf16 g_Qh[(size_t)8192 * 1024], g_Ql[(size_t)8192 * 1024];
__device__ bf16 g_Kh[(size_t)8192 * 1024], g_Kl[(size_t)8192 * 1024];
__device__ bf16 g_Vh[(size_t)8192 * 1024], g_Vl[(size_t)8192 * 1024];
__device__ bf16 g_Oh[(size_t)8192 * 1024], g_Ol[(size_t)8192 * 1024];
__device__ float g_rsin[S_ * HALF_];
__device__ float g_rcos[S_ * HALF_];

// ---------------------------------------------------------------------------
// helpers
// ---------------------------------------------------------------------------
__device__ __forceinline__ uint32_t smem_u32(const void* p) {
    uint32_t a;
    asm("{ .reg .u64 t; cvta.to.shared.u64 t, %1; cvt.u32.u64 %0, t; }"
        : "=r"(a) : "l"(p));
    return a;
}
// pack two f32 into bf16x2 (first arg -> low half = lower memory address)
__device__ __forceinline__ uint32_t pack2(float lo, float hi) {
    uint32_t r;
    asm("cvt.rn.bf16x2.f32 %0, %1, %2;" : "=r"(r) : "f"(hi), "f"(lo));
    return r;
}
__device__ __forceinline__ float lo_f(uint32_t p) {
    return __uint_as_float(p << 16);
}
__device__ __forceinline__ float hi_f(uint32_t p) {
    return __uint_as_float(p & 0xFFFF0000u);
}
#define SW128(o) ((o) ^ (((o) >> 3) & 0x70))

#define CP16(dst, src)                                                        \
    asm volatile("cp.async.cg.shared.global [%0], [%1], 16;" ::"r"(dst),      \
                 "l"(src))
#define CP_COMMIT() asm volatile("cp.async.commit_group;" ::: "memory")
#define CP_WAIT1() asm volatile("cp.async.wait_group 1;" ::: "memory")
#define CP_WAIT0() asm volatile("cp.async.wait_group 0;" ::: "memory")

__device__ __forceinline__ void ldm4(uint32_t* r, uint32_t addr) {
    asm volatile(
        "ldmatrix.sync.aligned.m8n8.x4.shared.b16 {%0,%1,%2,%3}, [%4];"
        : "=r"(r[0]), "=r"(r[1]), "=r"(r[2]), "=r"(r[3]) : "r"(addr));
}
__device__ __forceinline__ void ldm4t(uint32_t* r, uint32_t addr) {
    asm volatile(
        "ldmatrix.sync.aligned.m8n8.x4.trans.shared.b16 {%0,%1,%2,%3}, [%4];"
        : "=r"(r[0]), "=r"(r[1]), "=r"(r[2]), "=r"(r[3]) : "r"(addr));
}
__device__ __forceinline__ void mma_bf16(float* d, const uint32_t* a,
                                         const uint32_t* b) {
    asm volatile(
        "mma.sync.aligned.m16n8k16.row.col.f32.bf16.bf16.f32 "
        "{%0,%1,%2,%3},{%4,%5,%6,%7},{%8,%9},{%0,%1,%2,%3};"
        : "+f"(d[0]), "+f"(d[1]), "+f"(d[2]), "+f"(d[3])
        : "r"(a[0]), "r"(a[1]), "r"(a[2]), "r"(a[3]), "r"(b[0]), "r"(b[1]));
}

// ---------------------------------------------------------------------------
// fp32 -> bf16 hi/lo split (vectorized by 4)
// ---------------------------------------------------------------------------
__global__ void conv_split_kernel(const float* __restrict__ src,
                                  bf16* __restrict__ dh, bf16* __restrict__ dl,
                                  int n4) {
    int i = blockIdx.x * blockDim.x + threadIdx.x;
    if (i >= n4) return;
    float4 v = ((const float4*)src)[i];
    uint32_t h0 = pack2(v.x, v.y), h1 = pack2(v.z, v.w);
    uint32_t l0 = pack2(v.x - lo_f(h0), v.y - hi_f(h0));
    uint32_t l1 = pack2(v.z - lo_f(h1), v.w - hi_f(h1));
    ((uint2*)dh)[i] = make_uint2(h0, h1);
    ((uint2*)dl)[i] = make_uint2(l0, l1);
}

// ---------------------------------------------------------------------------
// RoPE sin/cos table: angles[s][p] = s * theta^(-p/32)
// ---------------------------------------------------------------------------
__global__ void rope_table_kernel() {
    int i = blockIdx.x * blockDim.x + threadIdx.x;
    if (i >= S_ * HALF_) return;
    int s = i >> 5;
    int p = i & 31;
    float invf = powf(10000.0f, -(float)p / 32.0f);
    float ang = (float)s * invf;
    g_rsin[i] = sinf(ang);
    g_rcos[i] = cosf(ang);
}

// ---------------------------------------------------------------------------
// Pipelined HMMA GEMM on pre-split bf16 inputs.
// C[m,e] = sum_d A[m,d]*W[e,d], 128x128 CTA tile, K-chunk 64, cp.async double
// buffer (2x64KB smem).  KIND 1: fused QKV (reads g_xh/g_Wch, writes split
// Q/K/V with RoPE+scale).  KIND 0: output proj (reads g_Oh/g_Woh, fp32 C).
// ---------------------------------------------------------------------------
#define GEMM_SMEM 131072

__device__ __forceinline__ void stage_chunk_g(const bf16* Ah, const bf16* Al,
                                              const bf16* Bh, const bf16* Bl,
                                              uint32_t sbuf, int m0, int n0,
                                              int ch, int tid) {
    const int r = tid >> 2;          // 0..127
    const int u0 = (tid & 3) * 2;    // 2 consecutive 16B units of 8
    const size_t arow = (size_t)(m0 + r) * D_ + ch * 64;
    const size_t brow = (size_t)(n0 + r) * D_ + ch * 64;
#pragma unroll
    for (int uu = 0; uu < 2; uu++) {
        const int u = u0 + uu;
        const uint32_t dst =
            sbuf + (uint32_t)(r * 128) +
            (((uint32_t)(u * 16)) ^ (((uint32_t)(r & 7)) << 4));
        CP16(dst, Ah + arow + u * 8);
        CP16(dst + 16384, Al + arow + u * 8);
        CP16(dst + 32768, Bh + brow + u * 8);
        CP16(dst + 49152, Bl + brow + u * 8);
    }
}

template <int KIND>
__global__ __launch_bounds__(512) void gemm_pipe(float* __restrict__ C) {
    extern __shared__ char smem[];
    const uint32_t sb = smem_u32(smem);
    const int tid = threadIdx.x;
    const int wid = tid >> 5;
    const int lane = tid & 31;
    const int m0 = blockIdx.y * 128;
    const int n0 = blockIdx.x * 128;
    const int wm = (wid & 3) * 32;
    const int wn = (wid >> 2) * 32;

    const bf16* Ah = KIND ? g_xh : g_Oh;
    const bf16* Al = KIND ? g_xl : g_Ol;
    const bf16* Bh = KIND ? g_Wch : g_Woh;
    const bf16* Bl = KIND ? g_Wcl : g_Wol;

    float acc[2][4][4];
#pragma unroll
    for (int mt = 0; mt < 2; mt++)
#pragma unroll
        for (int nt = 0; nt < 4; nt++)
#pragma unroll
            for (int i = 0; i < 4; i++) acc[mt][nt][i] = 0.0f;

    stage_chunk_g(Ah, Al, Bh, Bl, sb, m0, n0, 0, tid);
    CP_COMMIT();
    stage_chunk_g(Ah, Al, Bh, Bl, sb + 65536u, m0, n0, 1, tid);
    CP_COMMIT();

    for (int ch = 0; ch < 16; ch++) {
        CP_WAIT1();
        __syncthreads();
        const uint32_t sbuf = sb + (uint32_t)(ch & 1) * 65536u;

#pragma unroll
        for (int ks = 0; ks < 4; ks++) {
            const int k0 = ks * 16;
            uint32_t ah[2][4], al[2][4], bh[2][4], bl[2][4];
#pragma unroll
            for (int mt = 0; mt < 2; mt++) {
                int row = wm + mt * 16 + (lane & 15);
                int kc = k0 + ((lane >> 4) << 3);
                uint32_t addr =
                    sbuf + row * 128 + ((((kc >> 3) ^ (row & 7)) << 4));
                ldm4(ah[mt], addr);
                ldm4(al[mt], addr + 16384);
            }
#pragma unroll
            for (int bt = 0; bt < 2; bt++) {
                int row = wn + bt * 16 + ((lane >> 4) << 3) + (lane & 7);
                int kc = k0 + (((lane >> 3) & 1) << 3);
                uint32_t addr = sbuf + 32768 + row * 128 +
                                ((((kc >> 3) ^ (row & 7)) << 4));
                ldm4(bh[bt], addr);
                ldm4(bl[bt], addr + 16384);
            }
#pragma unroll
            for (int mt = 0; mt < 2; mt++)
#pragma unroll
                for (int nt = 0; nt < 4; nt++) {
                    const uint32_t* ph = &bh[nt >> 1][(nt & 1) * 2];
                    const uint32_t* pl = &bl[nt >> 1][(nt & 1) * 2];
                    mma_bf16(acc[mt][nt], ah[mt], ph);
                    mma_bf16(acc[mt][nt], ah[mt], pl);
                    mma_bf16(acc[mt][nt], al[mt], ph);
                }
        }
        __syncthreads();
        if (ch < 14)
            stage_chunk_g(Ah, Al, Bh, Bl, sb + (uint32_t)(ch & 1) * 65536u,
                          m0, n0, ch + 2, tid);
        CP_COMMIT();
    }

    // -------- epilogue --------
    const int rbase = m0 + wm + (lane >> 2);
    const int lcb = wn + (lane & 3) * 2;  // local col base in tile
#pragma unroll
    for (int mt = 0; mt < 2; mt++) {
#pragma unroll
        for (int half = 0; half < 2; half++) {
            const int m = rbase + mt * 16 + half * 8;
#pragma unroll
            for (int nt = 0; nt < 4; nt++) {
                float v0 = acc[mt][nt][half * 2 + 0];
                float v1 = acc[mt][nt][half * 2 + 1];
                if (KIND == 0) {
                    *(float2*)(C + (size_t)m * D_ + n0 + lcb + nt * 8) =
                        make_float2(v0, v1);
                } else {
                    const int sec = n0 >> 10;          // 0=q 1=k 2=v
                    const int gcol = (n0 & 1023) + lcb + nt * 8;
                    const int b = m >> 11;
                    const int s = m & (S_ - 1);
                    const int h = gcol >> 6;
                    const int t = gcol & 63;
                    if (sec < 2) {  // RoPE for q,k
                        int p = t >> 1;
                        float sn = g_rsin[s * HALF_ + p];
                        float cs = g_rcos[s * HALF_ + p];
                        float x0 = v0, x1 = v1;
                        v0 = x0 * cs - x1 * sn;
                        v1 = x0 * sn + x1 * cs;
                    }
                    if (sec == 0) { v0 *= SCALE_; v1 *= SCALE_; }
                    uint32_t hp = pack2(v0, v1);
                    uint32_t lp = pack2(v0 - lo_f(hp), v1 - hi_f(hp));
                    size_t offu =
                        ((size_t)((b * H_ + h) * S_ + s) * DK_ + t) >> 1;
                    if (sec == 0) {
                        ((uint32_t*)g_Qh)[offu] = hp;
                        ((uint32_t*)g_Ql)[offu] = lp;
                    } else if (sec == 1) {
                        ((uint32_t*)g_Kh)[offu] = hp;
                        ((uint32_t*)g_Kl)[offu] = lp;
                    } else {
                        ((uint32_t*)g_Vh)[offu] = hp;
                        ((uint32_t*)g_Vl)[offu] = lp;
                    }
                }
            }
        }
    }
}

// ---------------------------------------------------------------------------
// HMMA flash attention on pre-split bf16 Q/K/V (Q pre-scaled).
// CTA = (64-q-block, b*H+h); 4 warps; 64-key tiles; cp.async double buffer.
// Writes split bf16 O (hi/lo) for the output projection.
// ---------------------------------------------------------------------------
__device__ __forceinline__ void stage_kv(const bf16* Kh, const bf16* Kl,
                                         const bf16* Vh, const bf16* Vl,
                                         uint32_t sbuf, int kb, int tid) {
    const int r = tid >> 1;        // 0..63
    const int u0 = (tid & 1) * 4;  // 4 consecutive 16B units of 8
    const size_t row = (size_t)(kb * 64 + r) * DK_;
#pragma unroll
    for (int uu = 0; uu < 4; uu++) {
        const int u = u0 + uu;
        const uint32_t dst =
            sbuf + (uint32_t)(r * 128) +
            (((uint32_t)(u * 16)) ^ (((uint32_t)(r & 7)) << 4));
        CP16(dst, Kh + row + u * 8);
        CP16(dst + 8192, Kl + row + u * 8);
        CP16(dst + 16384, Vh + row + u * 8);
        CP16(dst + 24576, Vl + row + u * 8);
    }
}

__global__ __launch_bounds__(128) void attn_mma_kernel() {
    const int bh = blockIdx.y;
    const int b = bh >> 4, h = bh & 15;
    const int qb = blockIdx.x;
    const int tid = threadIdx.x;
    const int wid = tid >> 5;
    const int lane = tid & 31;

    const size_t head_off = (size_t)bh * S_ * DK_;
    const bf16* Qh = g_Qh + head_off + (size_t)qb * 64 * DK_;
    const bf16* Qlp = g_Ql + head_off + (size_t)qb * 64 * DK_;
    const bf16* Kh = g_Kh + head_off;
    const bf16* Kl = g_Kl + head_off;
    const bf16* Vh = g_Vh + head_off;
    const bf16* Vl = g_Vl + head_off;

    __shared__ __align__(128) char sm[65536];
    const uint32_t sb = smem_u32(sm);

    // ---- stage Q into buffer0, pull A-fragments to regs ----
#pragma unroll
    for (int it = 0; it < 4; it++) {
        int idx = it * 128 + tid;
        int r = idx >> 3, u = idx & 7;
        uint32_t off = (uint32_t)(r * 128) +
                       (((uint32_t)(u * 16)) ^ (((uint32_t)(r & 7)) << 4));
        *(uint4*)(sm + off) = *(const uint4*)(Qh + (size_t)r * DK_ + u * 8);
        *(uint4*)(sm + 8192 + off) =
            *(const uint4*)(Qlp + (size_t)r * DK_ + u * 8);
    }
    __syncthreads();

    uint32_t qh[4][4], ql[4][4];
#pragma unroll
    for (int kk = 0; kk < 4; kk++) {
        int row = wid * 16 + (lane & 15);
        int kbyte = kk * 32 + ((lane >> 4) << 4);
        uint32_t ad = sb + row * 128 +
                      (((uint32_t)kbyte) ^ (((uint32_t)(row & 7)) << 4));
        ldm4(qh[kk], ad);
        ldm4(ql[kk], ad + 8192);
    }
    __syncthreads();

    float oacc[8][4];
#pragma unroll
    for (int j = 0; j < 8; j++)
#pragma unroll
        for (int i = 0; i < 4; i++) oacc[j][i] = 0.0f;
    float m1 = -1e30f, m2 = -1e30f, l1 = 0.0f, l2 = 0.0f;

    // ---- KV pipeline prologue ----
    stage_kv(Kh, Kl, Vh, Vl, sb, 0, tid);
    CP_COMMIT();
    if (qb >= 1) stage_kv(Kh, Kl, Vh, Vl, sb + 32768u, 1, tid);
    CP_COMMIT();

    for (int kb = 0; kb <= qb; kb++) {
        if (kb == qb) { CP_WAIT0(); } else { CP_WAIT1(); }
        __syncthreads();
        const uint32_t sbuf = sb + (uint32_t)(kb & 1) * 32768u;

        // ---- S = Q K^T (split 3-mma) ----
        float sacc[8][4];
#pragma unroll
        for (int j = 0; j < 8; j++)
#pragma unroll
            for (int i = 0; i < 4; i++) sacc[j][i] = 0.0f;

#pragma unroll
        for (int kt = 0; kt < 4; kt++) {
#pragma unroll
            for (int kk = 0; kk < 4; kk++) {
                uint32_t khf[4], klf[4];
                int row = kt * 16 + ((lane >> 4) << 3) + (lane & 7);
                int kbyte = kk * 32 + (((lane >> 3) & 1) << 4);
                uint32_t ad = sbuf + row * 128 +
                              (((uint32_t)kbyte) ^
                               (((uint32_t)(row & 7)) << 4));
                ldm4(khf, ad);
                ldm4(klf, ad + 8192);
#pragma unroll
                for (int sub = 0; sub < 2; sub++) {
                    int j = kt * 2 + sub;
                    mma_bf16(sacc[j], qh[kk], &khf[sub * 2]);
                    mma_bf16(sacc[j], qh[kk], &klf[sub * 2]);
                    mma_bf16(sacc[j], ql[kk], &khf[sub * 2]);
                }
            }
        }

        // ---- causal mask (diagonal tile only) ----
        const int rq1 = qb * 64 + wid * 16 + (lane >> 2);
        const int rq2 = rq1 + 8;
        if (kb == qb) {
            const int cb = kb * 64 + (lane & 3) * 2;
#pragma unroll
            for (int j = 0; j < 8; j++) {
#pragma unroll
                for (int e = 0; e < 2; e++) {
                    int col = cb + j * 8 + e;
                    if (col > rq1) sacc[j][e] = -1e30f;
                    if (col > rq2) sacc[j][2 + e] = -1e30f;
                }
            }
        }

        // ---- online softmax (fragment layout) ----
        float mx1 = -1e30f, mx2 = -1e30f;
#pragma unroll
        for (int j = 0; j < 8; j++) {
            mx1 = fmaxf(mx1, fmaxf(sacc[j][0], sacc[j][1]));
            mx2 = fmaxf(mx2, fmaxf(sacc[j][2], sacc[j][3]));
        }
        mx1 = fmaxf(mx1, __shfl_xor_sync(0xFFFFFFFFu, mx1, 1));
        mx1 = fmaxf(mx1, __shfl_xor_sync(0xFFFFFFFFu, mx1, 2));
        mx2 = fmaxf(mx2, __shfl_xor_sync(0xFFFFFFFFu, mx2, 1));
        mx2 = fmaxf(mx2, __shfl_xor_sync(0xFFFFFFFFu, mx2, 2));
        float mn1 = fmaxf(m1, mx1);
        float mn2 = fmaxf(m2, mx2);
        float cor1 = __expf(m1 - mn1);
        float cor2 = __expf(m2 - mn2);
        m1 = mn1; m2 = mn2;
        float sum1 = 0.0f, sum2 = 0.0f;
#pragma unroll
        for (int j = 0; j < 8; j++) {
            sacc[j][0] = __expf(sacc[j][0] - mn1);
            sacc[j][1] = __expf(sacc[j][1] - mn1);
            sacc[j][2] = __expf(sacc[j][2] - mn2);
            sacc[j][3] = __expf(sacc[j][3] - mn2);
            sum1 += sacc[j][0] + sacc[j][1];
            sum2 += sacc[j][2] + sacc[j][3];
        }
        sum1 += __shfl_xor_sync(0xFFFFFFFFu, sum1, 1);
        sum1 += __shfl_xor_sync(0xFFFFFFFFu, sum1, 2);
        sum2 += __shfl_xor_sync(0xFFFFFFFFu, sum2, 1);
        sum2 += __shfl_xor_sync(0xFFFFFFFFu, sum2, 2);
        l1 = l1 * cor1 + sum1;
        l2 = l2 * cor2 + sum2;
#pragma unroll
        for (int j = 0; j < 8; j++) {
            oacc[j][0] *= cor1; oacc[j][1] *= cor1;
            oacc[j][2] *= cor2; oacc[j][3] *= cor2;
        }

        // ---- O += P V (P re-packed in-register, split 3-mma) ----
#pragma unroll
        for (int kk = 0; kk < 4; kk++) {
            uint32_t aPh[4], aPl[4];
            {
                const float* p0 = sacc[2 * kk];
                const float* p1 = sacc[2 * kk + 1];
                aPh[0] = pack2(p0[0], p0[1]);
                aPh[1] = pack2(p0[2], p0[3]);
                aPh[2] = pack2(p1[0], p1[1]);
                aPh[3] = pack2(p1[2], p1[3]);
                aPl[0] = pack2(p0[0] - lo_f(aPh[0]), p0[1] - hi_f(aPh[0]));
                aPl[1] = pack2(p0[2] - lo_f(aPh[1]), p0[3] - hi_f(aPh[1]));
                aPl[2] = pack2(p1[0] - lo_f(aPh[2]), p1[1] - hi_f(aPh[2]));
                aPl[3] = pack2(p1[2] - lo_f(aPh[3]), p1[3] - hi_f(aPh[3]));
            }
#pragma unroll
            for (int pr = 0; pr < 4; pr++) {
                uint32_t vhf[4], vlf[4];
                int key = kk * 16 + (((lane >> 3) & 1) << 3) + (lane & 7);
                int dbyte = pr * 32 + ((lane >> 4) << 4);
                uint32_t ad = sbuf + 16384 + key * 128 +
                              (((uint32_t)dbyte) ^
                               (((uint32_t)(key & 7)) << 4));
                ldm4t(vhf, ad);
                ldm4t(vlf, ad + 8192);
#pragma unroll
                for (int sub = 0; sub < 2; sub++) {
                    int j = pr * 2 + sub;
                    mma_bf16(oacc[j], aPh, &vhf[sub * 2]);
                    mma_bf16(oacc[j], aPh, &vlf[sub * 2]);
                    mma_bf16(oacc[j], aPl, &vhf[sub * 2]);
                }
            }
        }
        __syncthreads();
        if (kb + 2 <= qb)
            stage_kv(Kh, Kl, Vh, Vl, sb + (uint32_t)(kb & 1) * 32768u, kb + 2,
                     tid);
        CP_COMMIT();
    }

    // ---- write split O to g_Oh/g_Ol [b][s][h*64+d] ----
    const float inv1 = 1.0f / l1;
    const float inv2 = 1.0f / l2;
    const int rq1 = qb * 64 + wid * 16 + (lane >> 2);
    const int rq2 = rq1 + 8;
    const size_t ro1 = (size_t)(b * S_ + rq1) * D_ + h * DK_;
    const size_t ro2 = (size_t)(b * S_ + rq2) * D_ + h * DK_;
#pragma unroll
    for (int j = 0; j < 8; j++) {
        int col = j * 8 + (lane & 3) * 2;
        float a0 = oacc[j][0] * inv1, a1 = oacc[j][1] * inv1;
        uint32_t hp = pack2(a0, a1);
        uint32_t lp = pack2(a0 - lo_f(hp), a1 - hi_f(hp));
        ((uint32_t*)g_Oh)[(ro1 + col) >> 1] = hp;
        ((uint32_t*)g_Ol)[(ro1 + col) >> 1] = lp;
        a0 = oacc[j][2] * inv2; a1 = oacc[j][3] * inv2;
        hp = pack2(a0, a1);
        lp = pack2(a0 - lo_f(hp), a1 - hi_f(hp));
        ((uint32_t*)g_Oh)[(ro2 + col) >> 1] = hp;
        ((uint32_t*)g_Ol)[(ro2 + col) >> 1] = lp;
    }
}

// ---------------------------------------------------------------------------
extern "C" void kernel_launch(void* const* d_in, const int* in_sizes, int n_in,
                              void* d_out, int out_size) {
    const float* x = (const float*)d_in[0];
    const float* Wq = (const float*)d_in[1];
    const float* Wk = (const float*)d_in[2];
    const float* Wv = (const float*)d_in[3];
    const float* Wo = (const float*)d_in[4];

    bf16 *xh, *xl, *Wch, *Wcl, *Woh, *Wol;
    cudaGetSymbolAddress((void**)&xh, g_xh);
    cudaGetSymbolAddress((void**)&xl, g_xl);
    cudaGetSymbolAddress((void**)&Wch, g_Wch);
    cudaGetSymbolAddress((void**)&Wcl, g_Wcl);
    cudaGetSymbolAddress((void**)&Woh, g_Woh);
    cudaGetSymbolAddress((void**)&Wol, g_Wol);

    cudaFuncSetAttribute(gemm_pipe<0>,
                         cudaFuncAttributeMaxDynamicSharedMemorySize, GEMM_SMEM);
    cudaFuncSetAttribute(gemm_pipe<1>,
                         cudaFuncAttributeMaxDynamicSharedMemorySize, GEMM_SMEM);

    rope_table_kernel<<<(S_ * HALF_ + 255) / 256, 256>>>();

    const int NW = 1024 * 1024;  // one weight matrix
    conv_split_kernel<<<(8192 * 1024 / 4 + 255) / 256, 256>>>(x, xh, xl,
                                                              8192 * 1024 / 4);
    conv_split_kernel<<<(NW / 4 + 255) / 256, 256>>>(Wq, Wch, Wcl, NW / 4);
    conv_split_kernel<<<(NW / 4 + 255) / 256, 256>>>(Wk, Wch + NW, Wcl + NW,
                                                     NW / 4);
    conv_split_kernel<<<(NW / 4 + 255) / 256, 256>>>(Wv, Wch + 2 * NW,
                                                     Wcl + 2 * NW, NW / 4);
    conv_split_kernel<<<(NW / 4 + 255) / 256, 256>>>(Wo, Woh, Wol, NW / 4);

    gemm_pipe<1><<<dim3(24, 64), 512, GEMM_SMEM>>>(nullptr);  // fused QKV

    attn_mma_kernel<<<dim3(S_ / 64, B_ * H_), 128>>>();

    gemm_pipe<0><<<dim3(8, 64), 512, GEMM_SMEM>>>((float*)d_out);
}

// round 8
// speedup vs baseline: 4.5007x; 1.0068x over previous
#include <cuda_runtime.h>
#include <cuda_bf16.h>
#include <math.h>
#include <stdint.h>

#define B_ 4
#define S_ 2048
#define D_ 1024
#define H_ 16
#define DK_ 64
#define HALF_ 32
#define SCALE_ 0.125f

typedef __nv_bfloat16 bf16;

// ---------------------------------------------------------------------------
// Scratch (device globals: no allocation allowed)
// ---------------------------------------------------------------------------
__device__ bf16 g_xh[(size_t)8192 * 1024], g_xl[(size_t)8192 * 1024];
__device__ bf16 g_Wch[(size_t)3072 * 1024], g_Wcl[(size_t)3072 * 1024];
__device__ bf16 g_Woh[(size_t)1024 * 1024], g_Wol[(size_t)1024 * 1024];
__device__ bf16 g_Qh[(size_t)8192 * 1024], g_Ql[(size_t)8192 * 1024];
__device__ bf16 g_Kh[(size_t)8192 * 1024], g_Kl[(size_t)8192 * 1024];
__device__ bf16 g_Vh[(size_t)8192 * 1024], g_Vl[(size_t)8192 * 1024];
__device__ bf16 g_Oh[(size_t)8192 * 1024], g_Ol[(size_t)8192 * 1024];
__device__ float g_rsin[S_ * HALF_];
__device__ float g_rcos[S_ * HALF_];

// ---------------------------------------------------------------------------
// helpers
// ---------------------------------------------------------------------------
__device__ __forceinline__ uint32_t smem_u32(const void* p) {
    uint32_t a;
    asm("{ .reg .u64 t; cvta.to.shared.u64 t, %1; cvt.u32.u64 %0, t; }"
        : "=r"(a) : "l"(p));
    return a;
}
// pack two f32 into bf16x2 (first arg -> low half = lower memory address)
__device__ __forceinline__ uint32_t pack2(float lo, float hi) {
    uint32_t r;
    asm("cvt.rn.bf16x2.f32 %0, %1, %2;" : "=r"(r) : "f"(hi), "f"(lo));
    return r;
}
__device__ __forceinline__ float lo_f(uint32_t p) {
    return __uint_as_float(p << 16);
}
__device__ __forceinline__ float hi_f(uint32_t p) {
    return __uint_as_float(p & 0xFFFF0000u);
}

#define CP16(dst, src)                                                        \
    asm volatile("cp.async.cg.shared.global [%0], [%1], 16;" ::"r"(dst),      \
                 "l"(src))
#define CP_COMMIT() asm volatile("cp.async.commit_group;" ::: "memory")
#define CP_WAIT1() asm volatile("cp.async.wait_group 1;" ::: "memory")
#define CP_WAIT0() asm volatile("cp.async.wait_group 0;" ::: "memory")

__device__ __forceinline__ void ldm4(uint32_t* r, uint32_t addr) {
    asm volatile(
        "ldmatrix.sync.aligned.m8n8.x4.shared.b16 {%0,%1,%2,%3}, [%4];"
        : "=r"(r[0]), "=r"(r[1]), "=r"(r[2]), "=r"(r[3]) : "r"(addr));
}
__device__ __forceinline__ void ldm4t(uint32_t* r, uint32_t addr) {
    asm volatile(
        "ldmatrix.sync.aligned.m8n8.x4.trans.shared.b16 {%0,%1,%2,%3}, [%4];"
        : "=r"(r[0]), "=r"(r[1]), "=r"(r[2]), "=r"(r[3]) : "r"(addr));
}
__device__ __forceinline__ void mma_bf16(float* d, const uint32_t* a,
                                         const uint32_t* b) {
    asm volatile(
        "mma.sync.aligned.m16n8k16.row.col.f32.bf16.bf16.f32 "
        "{%0,%1,%2,%3},{%4,%5,%6,%7},{%8,%9},{%0,%1,%2,%3};"
        : "+f"(d[0]), "+f"(d[1]), "+f"(d[2]), "+f"(d[3])
        : "r"(a[0]), "r"(a[1]), "r"(a[2]), "r"(a[3]), "r"(b[0]), "r"(b[1]));
}

// ---------------------------------------------------------------------------
// fp32 -> bf16 hi/lo split (vectorized by 4)
// ---------------------------------------------------------------------------
__global__ void conv_split_kernel(const float* __restrict__ src,
                                  bf16* __restrict__ dh, bf16* __restrict__ dl,
                                  int n4) {
    int i = blockIdx.x * blockDim.x + threadIdx.x;
    if (i >= n4) return;
    float4 v = ((const float4*)src)[i];
    uint32_t h0 = pack2(v.x, v.y), h1 = pack2(v.z, v.w);
    uint32_t l0 = pack2(v.x - lo_f(h0), v.y - hi_f(h0));
    uint32_t l1 = pack2(v.z - lo_f(h1), v.w - hi_f(h1));
    ((uint2*)dh)[i] = make_uint2(h0, h1);
    ((uint2*)dl)[i] = make_uint2(l0, l1);
}

// ---------------------------------------------------------------------------
// RoPE sin/cos table: angles[s][p] = s * theta^(-p/32)
// ---------------------------------------------------------------------------
__global__ void rope_table_kernel() {
    int i = blockIdx.x * blockDim.x + threadIdx.x;
    if (i >= S_ * HALF_) return;
    int s = i >> 5;
    int p = i & 31;
    float invf = powf(10000.0f, -(float)p / 32.0f);
    float ang = (float)s * invf;
    g_rsin[i] = sinf(ang);
    g_rcos[i] = cosf(ang);
}

// ---------------------------------------------------------------------------
// Pipelined HMMA GEMM on pre-split bf16 inputs.
// 128x128 CTA tile, K-chunk 64, 3-stage cp.async pipeline (3x64KB smem),
// copy for ch+2 issued BEFORE the MMA phase of ch (one sync per chunk).
// KIND 1: fused QKV (writes split Q/K/V with RoPE+scale).  KIND 0: out proj.
// ---------------------------------------------------------------------------
#define GEMM_SMEM 196608

__device__ __forceinline__ void stage_chunk_g(const bf16* Ah, const bf16* Al,
                                              const bf16* Bh, const bf16* Bl,
                                              uint32_t sbuf, int m0, int n0,
                                              int ch, int tid) {
    const int r = tid >> 2;          // 0..127
    const int u0 = (tid & 3) * 2;    // 2 consecutive 16B units of 8
    const size_t arow = (size_t)(m0 + r) * D_ + ch * 64;
    const size_t brow = (size_t)(n0 + r) * D_ + ch * 64;
#pragma unroll
    for (int uu = 0; uu < 2; uu++) {
        const int u = u0 + uu;
        const uint32_t dst =
            sbuf + (uint32_t)(r * 128) +
            (((uint32_t)(u * 16)) ^ (((uint32_t)(r & 7)) << 4));
        CP16(dst, Ah + arow + u * 8);
        CP16(dst + 16384, Al + arow + u * 8);
        CP16(dst + 32768, Bh + brow + u * 8);
        CP16(dst + 49152, Bl + brow + u * 8);
    }
}

template <int KIND>
__global__ __launch_bounds__(512) void gemm_pipe(float* __restrict__ C) {
    extern __shared__ char smem[];
    const uint32_t sb = smem_u32(smem);
    const int tid = threadIdx.x;
    const int wid = tid >> 5;
    const int lane = tid & 31;
    const int m0 = blockIdx.y * 128;
    const int n0 = blockIdx.x * 128;
    const int wm = (wid & 3) * 32;
    const int wn = (wid >> 2) * 32;

    const bf16* Ah = KIND ? g_xh : g_Oh;
    const bf16* Al = KIND ? g_xl : g_Ol;
    const bf16* Bh = KIND ? g_Wch : g_Woh;
    const bf16* Bl = KIND ? g_Wcl : g_Wol;

    float acc[2][4][4];
#pragma unroll
    for (int mt = 0; mt < 2; mt++)
#pragma unroll
        for (int nt = 0; nt < 4; nt++)
#pragma unroll
            for (int i = 0; i < 4; i++) acc[mt][nt][i] = 0.0f;

    stage_chunk_g(Ah, Al, Bh, Bl, sb, m0, n0, 0, tid);
    CP_COMMIT();
    stage_chunk_g(Ah, Al, Bh, Bl, sb + 65536u, m0, n0, 1, tid);
    CP_COMMIT();

    int buf = 0;    // ch % 3
    int nbuf = 2;   // (ch+2) % 3
    for (int ch = 0; ch < 16; ch++) {
        CP_WAIT1();
        __syncthreads();
        // issue the copy for ch+2 BEFORE the MMA phase; its target buffer
        // (ch-1)%3 was fully consumed last iteration.
        if (ch < 14)
            stage_chunk_g(Ah, Al, Bh, Bl, sb + (uint32_t)nbuf * 65536u, m0,
                          n0, ch + 2, tid);
        CP_COMMIT();
        const uint32_t sbuf = sb + (uint32_t)buf * 65536u;

#pragma unroll
        for (int ks = 0; ks < 4; ks++) {
            const int k0 = ks * 16;
            uint32_t ah[2][4], al[2][4], bh[2][4], bl[2][4];
#pragma unroll
            for (int mt = 0; mt < 2; mt++) {
                int row = wm + mt * 16 + (lane & 15);
                int kc = k0 + ((lane >> 4) << 3);
                uint32_t addr =
                    sbuf + row * 128 + ((((kc >> 3) ^ (row & 7)) << 4));
                ldm4(ah[mt], addr);
                ldm4(al[mt], addr + 16384);
            }
#pragma unroll
            for (int bt = 0; bt < 2; bt++) {
                int row = wn + bt * 16 + ((lane >> 4) << 3) + (lane & 7);
                int kc = k0 + (((lane >> 3) & 1) << 3);
                uint32_t addr = sbuf + 32768 + row * 128 +
                                ((((kc >> 3) ^ (row & 7)) << 4));
                ldm4(bh[bt], addr);
                ldm4(bl[bt], addr + 16384);
            }
            // term-grouped: 8 independent accumulators per pass
#pragma unroll
            for (int mt = 0; mt < 2; mt++)
#pragma unroll
                for (int nt = 0; nt < 4; nt++)
                    mma_bf16(acc[mt][nt], ah[mt], &bh[nt >> 1][(nt & 1) * 2]);
#pragma unroll
            for (int mt = 0; mt < 2; mt++)
#pragma unroll
                for (int nt = 0; nt < 4; nt++)
                    mma_bf16(acc[mt][nt], ah[mt], &bl[nt >> 1][(nt & 1) * 2]);
#pragma unroll
            for (int mt = 0; mt < 2; mt++)
#pragma unroll
                for (int nt = 0; nt < 4; nt++)
                    mma_bf16(acc[mt][nt], al[mt], &bh[nt >> 1][(nt & 1) * 2]);
        }
        buf = (buf == 2) ? 0 : buf + 1;
        nbuf = (nbuf == 2) ? 0 : nbuf + 1;
    }

    // -------- epilogue --------
    const int rbase = m0 + wm + (lane >> 2);
    const int lcb = wn + (lane & 3) * 2;  // local col base in tile
#pragma unroll
    for (int mt = 0; mt < 2; mt++) {
#pragma unroll
        for (int half = 0; half < 2; half++) {
            const int m = rbase + mt * 16 + half * 8;
#pragma unroll
            for (int nt = 0; nt < 4; nt++) {
                float v0 = acc[mt][nt][half * 2 + 0];
                float v1 = acc[mt][nt][half * 2 + 1];
                if (KIND == 0) {
                    *(float2*)(C + (size_t)m * D_ + n0 + lcb + nt * 8) =
                        make_float2(v0, v1);
                } else {
                    const int sec = n0 >> 10;          // 0=q 1=k 2=v
                    const int gcol = (n0 & 1023) + lcb + nt * 8;
                    const int b = m >> 11;
                    const int s = m & (S_ - 1);
                    const int h = gcol >> 6;
                    const int t = gcol & 63;
                    if (sec < 2) {  // RoPE for q,k
                        int p = t >> 1;
                        float sn = g_rsin[s * HALF_ + p];
                        float cs = g_rcos[s * HALF_ + p];
                        float x0 = v0, x1 = v1;
                        v0 = x0 * cs - x1 * sn;
                        v1 = x0 * sn + x1 * cs;
                    }
                    if (sec == 0) { v0 *= SCALE_; v1 *= SCALE_; }
                    uint32_t hp = pack2(v0, v1);
                    uint32_t lp = pack2(v0 - lo_f(hp), v1 - hi_f(hp));
                    size_t offu =
                        ((size_t)((b * H_ + h) * S_ + s) * DK_ + t) >> 1;
                    if (sec == 0) {
                        ((uint32_t*)g_Qh)[offu] = hp;
                        ((uint32_t*)g_Ql)[offu] = lp;
                    } else if (sec == 1) {
                        ((uint32_t*)g_Kh)[offu] = hp;
                        ((uint32_t*)g_Kl)[offu] = lp;
                    } else {
                        ((uint32_t*)g_Vh)[offu] = hp;
                        ((uint32_t*)g_Vl)[offu] = lp;
                    }
                }
            }
        }
    }
}

// ---------------------------------------------------------------------------
// HMMA flash attention on pre-split bf16 Q/K/V (Q pre-scaled).
// CTA = (64-q-block, b*H+h); 4 warps; 64-key tiles; cp.async double buffer.
// Writes split bf16 O (hi/lo) for the output projection.
// ---------------------------------------------------------------------------
__device__ __forceinline__ void stage_kv(const bf16* Kh, const bf16* Kl,
                                         const bf16* Vh, const bf16* Vl,
                                         uint32_t sbuf, int kb, int tid) {
    const int r = tid >> 1;        // 0..63
    const int u0 = (tid & 1) * 4;  // 4 consecutive 16B units of 8
    const size_t row = (size_t)(kb * 64 + r) * DK_;
#pragma unroll
    for (int uu = 0; uu < 4; uu++) {
        const int u = u0 + uu;
        const uint32_t dst =
            sbuf + (uint32_t)(r * 128) +
            (((uint32_t)(u * 16)) ^ (((uint32_t)(r & 7)) << 4));
        CP16(dst, Kh + row + u * 8);
        CP16(dst + 8192, Kl + row + u * 8);
        CP16(dst + 16384, Vh + row + u * 8);
        CP16(dst + 24576, Vl + row + u * 8);
    }
}

__global__ __launch_bounds__(128) void attn_mma_kernel() {
    const int bh = blockIdx.y;
    const int b = bh >> 4, h = bh & 15;
    const int qb = blockIdx.x;
    const int tid = threadIdx.x;
    const int wid = tid >> 5;
    const int lane = tid & 31;

    const size_t head_off = (size_t)bh * S_ * DK_;
    const bf16* Qh = g_Qh + head_off + (size_t)qb * 64 * DK_;
    const bf16* Qlp = g_Ql + head_off + (size_t)qb * 64 * DK_;
    const bf16* Kh = g_Kh + head_off;
    const bf16* Kl = g_Kl + head_off;
    const bf16* Vh = g_Vh + head_off;
    const bf16* Vl = g_Vl + head_off;

    __shared__ __align__(128) char sm[65536];
    const uint32_t sb = smem_u32(sm);

    // ---- stage Q into buffer0, pull A-fragments to regs ----
#pragma unroll
    for (int it = 0; it < 4; it++) {
        int idx = it * 128 + tid;
        int r = idx >> 3, u = idx & 7;
        uint32_t off = (uint32_t)(r * 128) +
                       (((uint32_t)(u * 16)) ^ (((uint32_t)(r & 7)) << 4));
        *(uint4*)(sm + off) = *(const uint4*)(Qh + (size_t)r * DK_ + u * 8);
        *(uint4*)(sm + 8192 + off) =
            *(const uint4*)(Qlp + (size_t)r * DK_ + u * 8);
    }
    __syncthreads();

    uint32_t qh[4][4], ql[4][4];
#pragma unroll
    for (int kk = 0; kk < 4; kk++) {
        int row = wid * 16 + (lane & 15);
        int kbyte = kk * 32 + ((lane >> 4) << 4);
        uint32_t ad = sb + row * 128 +
                      (((uint32_t)kbyte) ^ (((uint32_t)(row & 7)) << 4));
        ldm4(qh[kk], ad);
        ldm4(ql[kk], ad + 8192);
    }
    __syncthreads();

    float oacc[8][4];
#pragma unroll
    for (int j = 0; j < 8; j++)
#pragma unroll
        for (int i = 0; i < 4; i++) oacc[j][i] = 0.0f;
    float m1 = -1e30f, m2 = -1e30f, l1 = 0.0f, l2 = 0.0f;

    // ---- KV pipeline prologue ----
    stage_kv(Kh, Kl, Vh, Vl, sb, 0, tid);
    CP_COMMIT();
    if (qb >= 1) stage_kv(Kh, Kl, Vh, Vl, sb + 32768u, 1, tid);
    CP_COMMIT();

    for (int kb = 0; kb <= qb; kb++) {
        if (kb == qb) { CP_WAIT0(); } else { CP_WAIT1(); }
        __syncthreads();
        const uint32_t sbuf = sb + (uint32_t)(kb & 1) * 32768u;

        // ---- S = Q K^T (split 3-mma) ----
        float sacc[8][4];
#pragma unroll
        for (int j = 0; j < 8; j++)
#pragma unroll
            for (int i = 0; i < 4; i++) sacc[j][i] = 0.0f;

#pragma unroll
        for (int kt = 0; kt < 4; kt++) {
#pragma unroll
            for (int kk = 0; kk < 4; kk++) {
                uint32_t khf[4], klf[4];
                int row = kt * 16 + ((lane >> 4) << 3) + (lane & 7);
                int kbyte = kk * 32 + (((lane >> 3) & 1) << 4);
                uint32_t ad = sbuf + row * 128 +
                              (((uint32_t)kbyte) ^
                               (((uint32_t)(row & 7)) << 4));
                ldm4(khf, ad);
                ldm4(klf, ad + 8192);
#pragma unroll
                for (int sub = 0; sub < 2; sub++) {
                    int j = kt * 2 + sub;
                    mma_bf16(sacc[j], qh[kk], &khf[sub * 2]);
                    mma_bf16(sacc[j], qh[kk], &klf[sub * 2]);
                    mma_bf16(sacc[j], ql[kk], &khf[sub * 2]);
                }
            }
        }

        // ---- causal mask (diagonal tile only) ----
        const int rq1 = qb * 64 + wid * 16 + (lane >> 2);
        const int rq2 = rq1 + 8;
        if (kb == qb) {
            const int cb = kb * 64 + (lane & 3) * 2;
#pragma unroll
            for (int j = 0; j < 8; j++) {
#pragma unroll
                for (int e = 0; e < 2; e++) {
                    int col = cb + j * 8 + e;
                    if (col > rq1) sacc[j][e] = -1e30f;
                    if (col > rq2) sacc[j][2 + e] = -1e30f;
                }
            }
        }

        // ---- online softmax (fragment layout) ----
        float mx1 = -1e30f, mx2 = -1e30f;
#pragma unroll
        for (int j = 0; j < 8; j++) {
            mx1 = fmaxf(mx1, fmaxf(sacc[j][0], sacc[j][1]));
            mx2 = fmaxf(mx2, fmaxf(sacc[j][2], sacc[j][3]));
        }
        mx1 = fmaxf(mx1, __shfl_xor_sync(0xFFFFFFFFu, mx1, 1));
        mx1 = fmaxf(mx1, __shfl_xor_sync(0xFFFFFFFFu, mx1, 2));
        mx2 = fmaxf(mx2, __shfl_xor_sync(0xFFFFFFFFu, mx2, 1));
        mx2 = fmaxf(mx2, __shfl_xor_sync(0xFFFFFFFFu, mx2, 2));
        float mn1 = fmaxf(m1, mx1);
        float mn2 = fmaxf(m2, mx2);
        float cor1 = __expf(m1 - mn1);
        float cor2 = __expf(m2 - mn2);
        m1 = mn1; m2 = mn2;
        float sum1 = 0.0f, sum2 = 0.0f;
#pragma unroll
        for (int j = 0; j < 8; j++) {
            sacc[j][0] = __expf(sacc[j][0] - mn1);
            sacc[j][1] = __expf(sacc[j][1] - mn1);
            sacc[j][2] = __expf(sacc[j][2] - mn2);
            sacc[j][3] = __expf(sacc[j][3] - mn2);
            sum1 += sacc[j][0] + sacc[j][1];
            sum2 += sacc[j][2] + sacc[j][3];
        }
        sum1 += __shfl_xor_sync(0xFFFFFFFFu, sum1, 1);
        sum1 += __shfl_xor_sync(0xFFFFFFFFu, sum1, 2);
        sum2 += __shfl_xor_sync(0xFFFFFFFFu, sum2, 1);
        sum2 += __shfl_xor_sync(0xFFFFFFFFu, sum2, 2);
        l1 = l1 * cor1 + sum1;
        l2 = l2 * cor2 + sum2;
#pragma unroll
        for (int j = 0; j < 8; j++) {
            oacc[j][0] *= cor1; oacc[j][1] *= cor1;
            oacc[j][2] *= cor2; oacc[j][3] *= cor2;
        }

        // ---- O += P V (P re-packed in-register, split 3-mma) ----
#pragma unroll
        for (int kk = 0; kk < 4; kk++) {
            uint32_t aPh[4], aPl[4];
            {
                const float* p0 = sacc[2 * kk];
                const float* p1 = sacc[2 * kk + 1];
                aPh[0] = pack2(p0[0], p0[1]);
                aPh[1] = pack2(p0[2], p0[3]);
                aPh[2] = pack2(p1[0], p1[1]);
                aPh[3] = pack2(p1[2], p1[3]);
                aPl[0] = pack2(p0[0] - lo_f(aPh[0]), p0[1] - hi_f(aPh[0]));
                aPl[1] = pack2(p0[2] - lo_f(aPh[1]), p0[3] - hi_f(aPh[1]));
                aPl[2] = pack2(p1[0] - lo_f(aPh[2]), p1[1] - hi_f(aPh[2]));
                aPl[3] = pack2(p1[2] - lo_f(aPh[3]), p1[3] - hi_f(aPh[3]));
            }
#pragma unroll
            for (int pr = 0; pr < 4; pr++) {
                uint32_t vhf[4], vlf[4];
                int key = kk * 16 + (((lane >> 3) & 1) << 3) + (lane & 7);
                int dbyte = pr * 32 + ((lane >> 4) << 4);
                uint32_t ad = sbuf + 16384 + key * 128 +
                              (((uint32_t)dbyte) ^
                               (((uint32_t)(key & 7)) << 4));
                ldm4t(vhf, ad);
                ldm4t(vlf, ad + 8192);
#pragma unroll
                for (int sub = 0; sub < 2; sub++) {
                    int j = pr * 2 + sub;
                    mma_bf16(oacc[j], aPh, &vhf[sub * 2]);
                    mma_bf16(oacc[j], aPh, &vlf[sub * 2]);
                    mma_bf16(oacc[j], aPl, &vhf[sub * 2]);
                }
            }
        }
        __syncthreads();
        if (kb + 2 <= qb)
            stage_kv(Kh, Kl, Vh, Vl, sb + (uint32_t)(kb & 1) * 32768u, kb + 2,
                     tid);
        CP_COMMIT();
    }

    // ---- write split O to g_Oh/g_Ol [b][s][h*64+d] ----
    const float inv1 = 1.0f / l1;
    const float inv2 = 1.0f / l2;
    const int rq1 = qb * 64 + wid * 16 + (lane >> 2);
    const int rq2 = rq1 + 8;
    const size_t ro1 = (size_t)(b * S_ + rq1) * D_ + h * DK_;
    const size_t ro2 = (size_t)(b * S_ + rq2) * D_ + h * DK_;
#pragma unroll
    for (int j = 0; j < 8; j++) {
        int col = j * 8 + (lane & 3) * 2;
        float a0 = oacc[j][0] * inv1, a1 = oacc[j][1] * inv1;
        uint32_t hp = pack2(a0, a1);
        uint32_t lp = pack2(a0 - lo_f(hp), a1 - hi_f(hp));
        ((uint32_t*)g_Oh)[(ro1 + col) >> 1] = hp;
        ((uint32_t*)g_Ol)[(ro1 + col) >> 1] = lp;
        a0 = oacc[j][2] * inv2; a1 = oacc[j][3] * inv2;
        hp = pack2(a0, a1);
        lp = pack2(a0 - lo_f(hp), a1 - hi_f(hp));
        ((uint32_t*)g_Oh)[(ro2 + col) >> 1] = hp;
        ((uint32_t*)g_Ol)[(ro2 + col) >> 1] = lp;
    }
}

// ---------------------------------------------------------------------------
extern "C" void kernel_launch(void* const* d_in, const int* in_sizes, int n_in,
                              void* d_out, int out_size) {
    const float* x = (const float*)d_in[0];
    const float* Wq = (const float*)d_in[1];
    const float* Wk = (const float*)d_in[2];
    const float* Wv = (const float*)d_in[3];
    const float* Wo = (const float*)d_in[4];

    bf16 *xh, *xl, *Wch, *Wcl, *Woh, *Wol;
    cudaGetSymbolAddress((void**)&xh, g_xh);
    cudaGetSymbolAddress((void**)&xl, g_xl);
    cudaGetSymbolAddress((void**)&Wch, g_Wch);
    cudaGetSymbolAddress((void**)&Wcl, g_Wcl);
    cudaGetSymbolAddress((void**)&Woh, g_Woh);
    cudaGetSymbolAddress((void**)&Wol, g_Wol);

    cudaFuncSetAttribute(gemm_pipe<0>,
                         cudaFuncAttributeMaxDynamicSharedMemorySize, GEMM_SMEM);
    cudaFuncSetAttribute(gemm_pipe<1>,
                         cudaFuncAttributeMaxDynamicSharedMemorySize, GEMM_SMEM);

    const int NW = 1024 * 1024;  // one weight matrix
    // launch order arranged so the ncu capture (-s 5 -c 1) profiles the
    // QKV GEMM: convs(1-4), rope(5), QKV(6).
    conv_split_kernel<<<(8192 * 1024 / 4 + 255) / 256, 256>>>(x, xh, xl,
                                                              8192 * 1024 / 4);
    conv_split_kernel<<<(NW / 4 + 255) / 256, 256>>>(Wq, Wch, Wcl, NW / 4);
    conv_split_kernel<<<(NW / 4 + 255) / 256, 256>>>(Wk, Wch + NW, Wcl + NW,
                                                     NW / 4);
    conv_split_kernel<<<(NW / 4 + 255) / 256, 256>>>(Wv, Wch + 2 * NW,
                                                     Wcl + 2 * NW, NW / 4);
    rope_table_kernel<<<(S_ * HALF_ + 255) / 256, 256>>>();

    gemm_pipe<1><<<dim3(24, 64), 512, GEMM_SMEM>>>(nullptr);  // fused QKV

    conv_split_kernel<<<(NW / 4 + 255) / 256, 256>>>(Wo, Woh, Wol, NW / 4);

    attn_mma_kernel<<<dim3(S_ / 64, B_ * H_), 128>>>();

    gemm_pipe<0><<<dim3(8, 64), 512, GEMM_SMEM>>>((float*)d_out);
}